// round 3
// baseline (speedup 1.0000x reference)
#include <cuda_runtime.h>
#include <cuda_bf16.h>
#include <math.h>

// ---------------- Problem constants ----------------
#define VOCAB 32000
#define DM    1024
#define NL    2
#define BB    8
#define SS    256
#define M_ROWS (BB*SS)          // 2048
#define G4D   (4*DM)            // 4096

// ---------------- Scratch (static device globals; no allocation) ----------------
__device__ float g_x[M_ROWS * DM];        // embeddings / layer input
__device__ float g_gx[M_ROWS * G4D];      // precomputed x-gates for current layer
__device__ float g_H0[M_ROWS * DM];       // layer-0 hidden outputs
__device__ float g_H1[M_ROWS * DM];       // layer-1 hidden outputs
__device__ float g_norm[M_ROWS * DM];     // rmsnormed
__device__ float g_hbuf[2 * BB * DM];     // double-buffered h state
__device__ unsigned int g_barrier_count;  // grid barrier ticket counter (wrap-safe)

// ---------------- Embedding gather ----------------
__global__ __launch_bounds__(256) void embed_kernel(const int* __restrict__ ids,
                                                    const float* __restrict__ emb) {
    int idx = blockIdx.x * blockDim.x + threadIdx.x;   // over M_ROWS * DM/4 float4
    int token = idx >> 8;                              // DM/4 = 256
    int d4 = idx & 255;
    int id = ids[token];
    reinterpret_cast<float4*>(g_x)[idx] =
        reinterpret_cast<const float4*>(emb + (size_t)id * DM)[d4];
}

// ---------------- SGEMM: C[M,N] = A[M,K] * B[N,K]^T (+ bias1[n] + bias2[n]) ----------------
// BM=BN=128, BK=8, 256 threads, 8x8 per thread. All dims here are multiples of tiles.
__global__ __launch_bounds__(256) void sgemm_nt_kernel(
    const float* __restrict__ A, const float* __restrict__ B,
    const float* __restrict__ bias1, const float* __restrict__ bias2,
    float* __restrict__ C, int M, int N, int K)
{
    const int BM = 128, BN = 128, BK = 8;
    __shared__ float As[BK][BM];
    __shared__ float Bs[BK][BN];
    int tid = threadIdx.x;
    int bm = blockIdx.y * BM;
    int bn = blockIdx.x * BN;

    int lrow = tid >> 1;           // 0..127
    int lk   = (tid & 1) << 2;     // 0 or 4
    const float* Ap = A + (size_t)(bm + lrow) * K + lk;
    const float* Bp = B + (size_t)(bn + lrow) * K + lk;

    int tx = tid & 15;             // n-tile 0..15
    int ty = tid >> 4;             // m-tile 0..15

    float acc[8][8];
    #pragma unroll
    for (int i = 0; i < 8; i++)
        #pragma unroll
        for (int j = 0; j < 8; j++) acc[i][j] = 0.f;

    for (int k0 = 0; k0 < K; k0 += BK) {
        float4 av = *reinterpret_cast<const float4*>(Ap + k0);
        float4 bv = *reinterpret_cast<const float4*>(Bp + k0);
        As[lk+0][lrow] = av.x; As[lk+1][lrow] = av.y;
        As[lk+2][lrow] = av.z; As[lk+3][lrow] = av.w;
        Bs[lk+0][lrow] = bv.x; Bs[lk+1][lrow] = bv.y;
        Bs[lk+2][lrow] = bv.z; Bs[lk+3][lrow] = bv.w;
        __syncthreads();
        #pragma unroll
        for (int kk = 0; kk < BK; kk++) {
            float a[8], b[8];
            *reinterpret_cast<float4*>(&a[0]) = *reinterpret_cast<const float4*>(&As[kk][ty*8]);
            *reinterpret_cast<float4*>(&a[4]) = *reinterpret_cast<const float4*>(&As[kk][ty*8+4]);
            *reinterpret_cast<float4*>(&b[0]) = *reinterpret_cast<const float4*>(&Bs[kk][tx*8]);
            *reinterpret_cast<float4*>(&b[4]) = *reinterpret_cast<const float4*>(&Bs[kk][tx*8+4]);
            #pragma unroll
            for (int i = 0; i < 8; i++)
                #pragma unroll
                for (int j = 0; j < 8; j++)
                    acc[i][j] = fmaf(a[i], b[j], acc[i][j]);
        }
        __syncthreads();
    }

    float badd[8];
    #pragma unroll
    for (int j = 0; j < 8; j++) {
        int n = bn + tx*8 + j;
        float bsum = 0.f;
        if (bias1) bsum += bias1[n];
        if (bias2) bsum += bias2[n];
        badd[j] = bsum;
    }
    #pragma unroll
    for (int i = 0; i < 8; i++) {
        float* crow = C + (size_t)(bm + ty*8 + i) * N + bn + tx*8;
        #pragma unroll
        for (int j = 0; j < 8; j += 4) {
            float4 v;
            v.x = acc[i][j+0] + badd[j+0];
            v.y = acc[i][j+1] + badd[j+1];
            v.z = acc[i][j+2] + badd[j+2];
            v.w = acc[i][j+3] + badd[j+3];
            *reinterpret_cast<float4*>(crow + j) = v;
        }
    }
}

// ---------------- Grid barrier (persistent kernel, 128 co-resident blocks) ----------------
__device__ __forceinline__ void grid_barrier() {
    __threadfence();               // make this thread's global writes visible
    __syncthreads();
    if (threadIdx.x == 0) {
        unsigned int ticket = atomicAdd(&g_barrier_count, 1);
        unsigned int target = ticket - (ticket % gridDim.x) + gridDim.x;
        volatile unsigned int* p = &g_barrier_count;
        while ((int)(*p - target) < 0) { }
    }
    __syncthreads();
}

__device__ __forceinline__ float sigmoidf_(float x) { return 1.f / (1.f + expf(-x)); }

// ---------------- LSTM layer (persistent; one grid barrier per timestep) ----------------
// Gx: [B*S][4096] precomputed x@Wx^T + bx + bh, row index = b*S + t
// Wh: [4096][1024]. H out: [B*S][1024]. hn/cn: [B][1024] (into d_out).
// Gates chunk order i,f,o,g -> gate row = chunk*1024 + d.
#define LSTM_BLOCKS 128
#define SH_STRIDE 1028   // pad to kill 8-way bank conflicts (1028*4 bytes, 16B-aligned)

__global__ __launch_bounds__(256) void lstm_layer_kernel(
    const float* __restrict__ Gx, const float* __restrict__ Wh,
    float* __restrict__ H, float* __restrict__ hn, float* __restrict__ cn)
{
    __shared__ float sh[BB * SH_STRIDE];   // h_prev staged, padded rows
    __shared__ float sg[4][8][8];          // gates [chunk][d_local][b]

    int tid = threadIdx.x;
    int r = tid >> 3;              // 0..31 : chunk*8 + d_local
    int b = tid & 7;
    int chunk = r >> 3;
    int dl = r & 7;
    int d = blockIdx.x * 8 + dl;   // 128 blocks * 8 = 1024 d's
    int grow = chunk * DM + d;     // gate row
    const float4* w4 = reinterpret_cast<const float4*>(Wh + (size_t)grow * DM);

    // cell state for update threads (tid < 64): (d_local, b) = (tid/8, tid%8)
    float c_state = 0.f;
    int u_dl = tid >> 3;           // valid when tid < 64
    int u_b  = tid & 7;
    int u_d  = blockIdx.x * 8 + u_dl;

    for (int t = 0; t < SS; t++) {
        if (t > 0) {
            // stage h_prev (written last step, possibly by other SMs) -> SMEM, bypass L1
            const float4* hb4 = reinterpret_cast<const float4*>(g_hbuf + ((t-1)&1) * (BB*DM));
            for (int i = tid; i < BB * (DM/4); i += 256) {
                int bb = i >> 8;           // DM/4 = 256
                int k4 = i & 255;
                float4 v = __ldcg(hb4 + i);
                *reinterpret_cast<float4*>(&sh[bb * SH_STRIDE + k4 * 4]) = v;
            }
        }
        __syncthreads();

        float acc = Gx[((size_t)(b * SS + t)) * G4D + grow];
        if (t > 0) {
            const float4* h4 = reinterpret_cast<const float4*>(&sh[b * SH_STRIDE]);
            float a0 = 0.f, a1 = 0.f, a2 = 0.f, a3 = 0.f;
            #pragma unroll 8
            for (int k = 0; k < DM/4; k++) {
                float4 w = w4[k];
                float4 h = h4[k];
                a0 = fmaf(w.x, h.x, a0);
                a1 = fmaf(w.y, h.y, a1);
                a2 = fmaf(w.z, h.z, a2);
                a3 = fmaf(w.w, h.w, a3);
            }
            acc += (a0 + a1) + (a2 + a3);
        }
        sg[chunk][dl][b] = acc;
        __syncthreads();

        if (tid < 64) {
            float gi = sg[0][u_dl][u_b];
            float gf = sg[1][u_dl][u_b];
            float go = sg[2][u_dl][u_b];
            float gg = sg[3][u_dl][u_b];
            float i_s = sigmoidf_(gi);
            float f_s = sigmoidf_(gf);
            float o_s = sigmoidf_(go);
            c_state = f_s * c_state + i_s * tanhf(gg);
            float h_new = o_s * tanhf(c_state);
            H[((size_t)(u_b * SS + t)) * DM + u_d] = h_new;
            g_hbuf[(t&1) * (BB*DM) + u_b * DM + u_d] = h_new;
            if (t == SS - 1) {
                hn[u_b * DM + u_d] = h_new;
                cn[u_b * DM + u_d] = c_state;
            }
        }
        grid_barrier();
    }
}

// ---------------- RMSNorm (one block per row) ----------------
__global__ __launch_bounds__(256) void rmsnorm_kernel(const float* __restrict__ in,
                                                      const float* __restrict__ w) {
    int row = blockIdx.x;
    int tid = threadIdx.x;
    const float4* r4 = reinterpret_cast<const float4*>(in + (size_t)row * DM);
    float4 v = r4[tid];            // DM/4 == 256 == blockDim
    float s = v.x*v.x + v.y*v.y + v.z*v.z + v.w*v.w;
    #pragma unroll
    for (int o = 16; o; o >>= 1) s += __shfl_xor_sync(0xFFFFFFFFu, s, o);
    __shared__ float red[8];
    if ((tid & 31) == 0) red[tid >> 5] = s;
    __syncthreads();
    float tot = red[0]+red[1]+red[2]+red[3]+red[4]+red[5]+red[6]+red[7];
    float scale = rsqrtf(tot * (1.f/ (float)DM) + 1e-5f);
    float4 wv = reinterpret_cast<const float4*>(w)[tid];
    float4 o4;
    o4.x = v.x * scale * wv.x;
    o4.y = v.y * scale * wv.y;
    o4.z = v.z * scale * wv.z;
    o4.w = v.w * scale * wv.w;
    reinterpret_cast<float4*>(g_norm + (size_t)row * DM)[tid] = o4;
}

// ---------------- Launch ----------------
extern "C" void kernel_launch(void* const* d_in, const int* in_sizes, int n_in,
                              void* d_out, int out_size) {
    const int*   ids = (const int*)d_in[0];
    const float* emb = (const float*)d_in[1];
    const float* Wx  = (const float*)d_in[2];
    const float* bx  = (const float*)d_in[3];
    const float* Wh  = (const float*)d_in[4];
    const float* bh  = (const float*)d_in[5];
    const float* nw  = (const float*)d_in[6];
    const float* ow  = (const float*)d_in[7];

    float* out = (float*)d_out;
    float* logits = out;
    float* hn = out + (size_t)M_ROWS * VOCAB;   // [L,B,D]
    float* cn = hn + (size_t)NL * BB * DM;      // [L,B,D]

    // device symbol addresses (query only; no allocation)
    float *px, *pgx, *pH0, *pH1, *pnorm;
    cudaGetSymbolAddress((void**)&px,    g_x);
    cudaGetSymbolAddress((void**)&pgx,   g_gx);
    cudaGetSymbolAddress((void**)&pH0,   g_H0);
    cudaGetSymbolAddress((void**)&pH1,   g_H1);
    cudaGetSymbolAddress((void**)&pnorm, g_norm);

    // 1. embeddings
    embed_kernel<<<M_ROWS * (DM/4) / 256, 256>>>(ids, emb);

    // 2. layer 0 x-gates: [2048,1024] x [4096,1024]^T (+bx0+bh0)
    sgemm_nt_kernel<<<dim3(G4D/128, M_ROWS/128), 256>>>(
        px, Wx, bx, bh, pgx, M_ROWS, G4D, DM);

    // 3. layer 0 recurrence
    lstm_layer_kernel<<<LSTM_BLOCKS, 256>>>(pgx, Wh, pH0, hn, cn);

    // 4. layer 1 x-gates from H0
    sgemm_nt_kernel<<<dim3(G4D/128, M_ROWS/128), 256>>>(
        pH0, Wx + (size_t)G4D*DM, bx + G4D, bh + G4D, pgx, M_ROWS, G4D, DM);

    // 5. layer 1 recurrence
    lstm_layer_kernel<<<LSTM_BLOCKS, 256>>>(pgx, Wh + (size_t)G4D*DM, pH1,
                                            hn + BB*DM, cn + BB*DM);

    // 6. RMSNorm
    rmsnorm_kernel<<<M_ROWS, 256>>>(pH1, nw);

    // 7. logits: [2048,1024] x [32000,1024]^T
    sgemm_nt_kernel<<<dim3(VOCAB/128, M_ROWS/128), 256>>>(
        pnorm, ow, nullptr, nullptr, logits, M_ROWS, VOCAB, DM);
}

// round 4
// speedup vs baseline: 2.6917x; 2.6917x over previous
#include <cuda_runtime.h>
#include <cuda_bf16.h>
#include <math.h>

// ---------------- Problem constants ----------------
#define VOCAB 32000
#define DM    1024
#define NL    2
#define BB    8
#define SS    256
#define M_ROWS (BB*SS)          // 2048
#define G4D   (4*DM)            // 4096

// ---------------- Scratch (static device globals; no allocation) ----------------
__device__ float g_x[M_ROWS * DM];        // embeddings / layer input
__device__ float g_gx[M_ROWS * G4D];      // precomputed x-gates for current layer
__device__ float g_H0[M_ROWS * DM];       // layer-0 hidden outputs
__device__ float g_H1[M_ROWS * DM];       // layer-1 hidden outputs
__device__ float g_norm[M_ROWS * DM];     // rmsnormed
__device__ float g_hbuf[2 * BB * DM];     // double-buffered h state
__device__ unsigned int g_barrier_count;  // grid barrier ticket counter (wrap-safe)

// ---------------- Embedding gather ----------------
__global__ __launch_bounds__(256) void embed_kernel(const int* __restrict__ ids,
                                                    const float* __restrict__ emb) {
    int idx = blockIdx.x * blockDim.x + threadIdx.x;   // over M_ROWS * DM/4 float4
    int token = idx >> 8;                              // DM/4 = 256
    int d4 = idx & 255;
    int id = ids[token];
    reinterpret_cast<float4*>(g_x)[idx] =
        reinterpret_cast<const float4*>(emb + (size_t)id * DM)[d4];
}

// ---------------- SGEMM: C[M,N] = A[M,K] * B[N,K]^T (+ bias1[n] + bias2[n]) ----------------
// BM=BN=128, BK=8, 256 threads, 8x8 per thread. All dims here are multiples of tiles.
__global__ __launch_bounds__(256) void sgemm_nt_kernel(
    const float* __restrict__ A, const float* __restrict__ B,
    const float* __restrict__ bias1, const float* __restrict__ bias2,
    float* __restrict__ C, int M, int N, int K)
{
    const int BM = 128, BN = 128, BK = 8;
    __shared__ float As[BK][BM];
    __shared__ float Bs[BK][BN];
    int tid = threadIdx.x;
    int bm = blockIdx.y * BM;
    int bn = blockIdx.x * BN;

    int lrow = tid >> 1;           // 0..127
    int lk   = (tid & 1) << 2;     // 0 or 4
    const float* Ap = A + (size_t)(bm + lrow) * K + lk;
    const float* Bp = B + (size_t)(bn + lrow) * K + lk;

    int tx = tid & 15;             // n-tile 0..15
    int ty = tid >> 4;             // m-tile 0..15

    float acc[8][8];
    #pragma unroll
    for (int i = 0; i < 8; i++)
        #pragma unroll
        for (int j = 0; j < 8; j++) acc[i][j] = 0.f;

    for (int k0 = 0; k0 < K; k0 += BK) {
        float4 av = *reinterpret_cast<const float4*>(Ap + k0);
        float4 bv = *reinterpret_cast<const float4*>(Bp + k0);
        As[lk+0][lrow] = av.x; As[lk+1][lrow] = av.y;
        As[lk+2][lrow] = av.z; As[lk+3][lrow] = av.w;
        Bs[lk+0][lrow] = bv.x; Bs[lk+1][lrow] = bv.y;
        Bs[lk+2][lrow] = bv.z; Bs[lk+3][lrow] = bv.w;
        __syncthreads();
        #pragma unroll
        for (int kk = 0; kk < BK; kk++) {
            float a[8], b[8];
            *reinterpret_cast<float4*>(&a[0]) = *reinterpret_cast<const float4*>(&As[kk][ty*8]);
            *reinterpret_cast<float4*>(&a[4]) = *reinterpret_cast<const float4*>(&As[kk][ty*8+4]);
            *reinterpret_cast<float4*>(&b[0]) = *reinterpret_cast<const float4*>(&Bs[kk][tx*8]);
            *reinterpret_cast<float4*>(&b[4]) = *reinterpret_cast<const float4*>(&Bs[kk][tx*8+4]);
            #pragma unroll
            for (int i = 0; i < 8; i++)
                #pragma unroll
                for (int j = 0; j < 8; j++)
                    acc[i][j] = fmaf(a[i], b[j], acc[i][j]);
        }
        __syncthreads();
    }

    float badd[8];
    #pragma unroll
    for (int j = 0; j < 8; j++) {
        int n = bn + tx*8 + j;
        float bsum = 0.f;
        if (bias1) bsum += bias1[n];
        if (bias2) bsum += bias2[n];
        badd[j] = bsum;
    }
    #pragma unroll
    for (int i = 0; i < 8; i++) {
        float* crow = C + (size_t)(bm + ty*8 + i) * N + bn + tx*8;
        #pragma unroll
        for (int j = 0; j < 8; j += 4) {
            float4 v;
            v.x = acc[i][j+0] + badd[j+0];
            v.y = acc[i][j+1] + badd[j+1];
            v.z = acc[i][j+2] + badd[j+2];
            v.w = acc[i][j+3] + badd[j+3];
            *reinterpret_cast<float4*>(crow + j) = v;
        }
    }
}

// ---------------- Grid barrier (persistent kernel, 128 co-resident blocks) ----------------
__device__ __forceinline__ void grid_barrier() {
    __threadfence();               // make this thread's global writes visible
    __syncthreads();
    if (threadIdx.x == 0) {
        unsigned int ticket = atomicAdd(&g_barrier_count, 1);
        unsigned int target = ticket - (ticket % gridDim.x) + gridDim.x;
        volatile unsigned int* p = &g_barrier_count;
        while ((int)(*p - target) < 0) { }
    }
    __syncthreads();
}

__device__ __forceinline__ float sigmoidf_(float x) { return 1.f / (1.f + expf(-x)); }

// ---------------- LSTM layer (persistent; Wh register-resident) ----------------
// 128 blocks x 512 threads. Block owns 32 gate rows (4 chunks x 8 d's).
// Thread (warp w = k-slice of 64, lane = row 0..31) holds Wh[row, 64k] in 16 float4 regs.
// Per step: h staged to SMEM once; inner loop = broadcast LDS + FFMA only (zero LDG).
// Cross-warp k-reduction via padded SMEM; activation by 64 threads holding c in regs.
#define LSTM_BLOCKS 128
#define LSTM_THREADS 512

__global__ __launch_bounds__(LSTM_THREADS, 1) void lstm_layer_kernel(
    const float* __restrict__ Gx, const float* __restrict__ Wh,
    float* __restrict__ H, float* __restrict__ hn, float* __restrict__ cn)
{
    __shared__ float4 sh4[BB * 256];       // h_prev: [b][k4], 32KB (broadcast reads)
    __shared__ float  sred[16 * 288];      // partials: [w][lane*9 + b], stride-9 pad, 18KB
    __shared__ float  sgate[256];          // gates: [r][b]

    int tid  = threadIdx.x;
    int w    = tid >> 5;                   // warp id = k-slice 0..15 (k in [w*64, w*64+64))
    int lane = tid & 31;                   // lane = row 0..31
    int chunk = lane >> 3, dl = lane & 7;
    int d    = blockIdx.x * 8 + dl;
    int grow = chunk * DM + d;             // gate row in [0,4096)

    // One-time: load this thread's Wh slice into registers (64 regs).
    float4 wreg[16];
    {
        const float4* wrow = reinterpret_cast<const float4*>(Wh + (size_t)grow * DM) + w * 16;
        #pragma unroll
        for (int i = 0; i < 16; i++) wreg[i] = wrow[i];
    }

    // Reduction thread mapping (tid < 256): rr = row, bb = batch
    int rr = tid >> 3, bb = tid & 7;
    int grow_red = (rr >> 3) * DM + blockIdx.x * 8 + (rr & 7);

    // Activation thread mapping (tid < 64): a_dl, a_b; c lives in regs for all 256 steps
    float c_state = 0.f;
    int a_dl = tid >> 3, a_b = tid & 7;
    int a_d  = blockIdx.x * 8 + a_dl;

    for (int t = 0; t < SS; t++) {
        if (t > 0) {
            // stage h_prev (written last step by other SMs) -> SMEM, bypass L1
            const float4* hb4 = reinterpret_cast<const float4*>(g_hbuf + ((t-1)&1) * (BB*DM));
            #pragma unroll
            for (int i = tid; i < BB * 256; i += LSTM_THREADS)
                sh4[i] = __ldcg(hb4 + i);
        }
        __syncthreads();

        // prefetch Gx gate value (used after reduction)
        float gx = 0.f;
        if (tid < 256)
            gx = __ldg(Gx + (size_t)(bb * SS + t) * G4D + grow_red);

        // partial dot products: 8 independent accumulator chains (one per batch)
        float acc[8];
        #pragma unroll
        for (int b = 0; b < 8; b++) acc[b] = 0.f;
        if (t > 0) {
            const float4* shw = &sh4[w * 16];
            #pragma unroll
            for (int k4 = 0; k4 < 16; k4++) {
                float4 wv = wreg[k4];
                #pragma unroll
                for (int b = 0; b < 8; b++) {
                    float4 h = shw[b * 256 + k4];     // broadcast across warp lanes
                    acc[b] = fmaf(wv.x, h.x, acc[b]);
                    acc[b] = fmaf(wv.y, h.y, acc[b]);
                    acc[b] = fmaf(wv.z, h.z, acc[b]);
                    acc[b] = fmaf(wv.w, h.w, acc[b]);
                }
            }
        }

        // write partials (stride-9 pad -> conflict-free)
        float* pr = &sred[(w * 32 + lane) * 9];
        #pragma unroll
        for (int b = 0; b < 8; b++) pr[b] = acc[b];
        __syncthreads();

        // reduce over 16 k-slices, add Gx, stage gate
        if (tid < 256) {
            float s = gx;
            #pragma unroll
            for (int ww = 0; ww < 16; ww++)
                s += sred[ww * 288 + rr * 9 + bb];
            sgate[rr * 8 + bb] = s;
        }
        __syncthreads();

        // activation + state update
        if (tid < 64) {
            float gi = sgate[(0  + a_dl) * 8 + a_b];
            float gf = sgate[(8  + a_dl) * 8 + a_b];
            float go = sgate[(16 + a_dl) * 8 + a_b];
            float gg = sgate[(24 + a_dl) * 8 + a_b];
            float i_s = sigmoidf_(gi);
            float f_s = sigmoidf_(gf);
            float o_s = sigmoidf_(go);
            c_state = f_s * c_state + i_s * tanhf(gg);
            float h_new = o_s * tanhf(c_state);
            H[((size_t)(a_b * SS + t)) * DM + a_d] = h_new;
            g_hbuf[(t & 1) * (BB * DM) + a_b * DM + a_d] = h_new;
            if (t == SS - 1) {
                hn[a_b * DM + a_d] = h_new;
                cn[a_b * DM + a_d] = c_state;
            }
        }
        grid_barrier();
    }
}

// ---------------- RMSNorm (one block per row) ----------------
__global__ __launch_bounds__(256) void rmsnorm_kernel(const float* __restrict__ in,
                                                      const float* __restrict__ w) {
    int row = blockIdx.x;
    int tid = threadIdx.x;
    const float4* r4 = reinterpret_cast<const float4*>(in + (size_t)row * DM);
    float4 v = r4[tid];            // DM/4 == 256 == blockDim
    float s = v.x*v.x + v.y*v.y + v.z*v.z + v.w*v.w;
    #pragma unroll
    for (int o = 16; o; o >>= 1) s += __shfl_xor_sync(0xFFFFFFFFu, s, o);
    __shared__ float red[8];
    if ((tid & 31) == 0) red[tid >> 5] = s;
    __syncthreads();
    float tot = red[0]+red[1]+red[2]+red[3]+red[4]+red[5]+red[6]+red[7];
    float scale = rsqrtf(tot * (1.f/ (float)DM) + 1e-5f);
    float4 wv = reinterpret_cast<const float4*>(w)[tid];
    float4 o4;
    o4.x = v.x * scale * wv.x;
    o4.y = v.y * scale * wv.y;
    o4.z = v.z * scale * wv.z;
    o4.w = v.w * scale * wv.w;
    reinterpret_cast<float4*>(g_norm + (size_t)row * DM)[tid] = o4;
}

// ---------------- Launch ----------------
extern "C" void kernel_launch(void* const* d_in, const int* in_sizes, int n_in,
                              void* d_out, int out_size) {
    const int*   ids = (const int*)d_in[0];
    const float* emb = (const float*)d_in[1];
    const float* Wx  = (const float*)d_in[2];
    const float* bx  = (const float*)d_in[3];
    const float* Wh  = (const float*)d_in[4];
    const float* bh  = (const float*)d_in[5];
    const float* nw  = (const float*)d_in[6];
    const float* ow  = (const float*)d_in[7];

    float* out = (float*)d_out;
    float* logits = out;
    float* hn = out + (size_t)M_ROWS * VOCAB;   // [L,B,D]
    float* cn = hn + (size_t)NL * BB * DM;      // [L,B,D]

    // device symbol addresses (query only; no allocation)
    float *px, *pgx, *pH0, *pH1, *pnorm;
    cudaGetSymbolAddress((void**)&px,    g_x);
    cudaGetSymbolAddress((void**)&pgx,   g_gx);
    cudaGetSymbolAddress((void**)&pH0,   g_H0);
    cudaGetSymbolAddress((void**)&pH1,   g_H1);
    cudaGetSymbolAddress((void**)&pnorm, g_norm);

    // 1. embeddings
    embed_kernel<<<M_ROWS * (DM/4) / 256, 256>>>(ids, emb);

    // 2. layer 0 x-gates: [2048,1024] x [4096,1024]^T (+bx0+bh0)
    sgemm_nt_kernel<<<dim3(G4D/128, M_ROWS/128), 256>>>(
        px, Wx, bx, bh, pgx, M_ROWS, G4D, DM);

    // 3. layer 0 recurrence
    lstm_layer_kernel<<<LSTM_BLOCKS, LSTM_THREADS>>>(pgx, Wh, pH0, hn, cn);

    // 4. layer 1 x-gates from H0
    sgemm_nt_kernel<<<dim3(G4D/128, M_ROWS/128), 256>>>(
        pH0, Wx + (size_t)G4D*DM, bx + G4D, bh + G4D, pgx, M_ROWS, G4D, DM);

    // 5. layer 1 recurrence
    lstm_layer_kernel<<<LSTM_BLOCKS, LSTM_THREADS>>>(pgx, Wh + (size_t)G4D*DM, pH1,
                                                     hn + BB*DM, cn + BB*DM);

    // 6. RMSNorm
    rmsnorm_kernel<<<M_ROWS, 256>>>(pH1, nw);

    // 7. logits: [2048,1024] x [32000,1024]^T
    sgemm_nt_kernel<<<dim3(VOCAB/128, M_ROWS/128), 256>>>(
        pnorm, ow, nullptr, nullptr, logits, M_ROWS, VOCAB, DM);
}

// round 8
// speedup vs baseline: 3.9424x; 1.4646x over previous
#include <cuda_runtime.h>
#include <cuda_bf16.h>
#include <math.h>
#include <stdint.h>

// ---------------- Problem constants ----------------
#define VOCAB 32000
#define DM    1024
#define NL    2
#define BB    8
#define SS    256
#define M_ROWS (BB*SS)          // 2048
#define G4D   (4*DM)            // 4096

// ---------------- Scratch (static device globals; no allocation) ----------------
__device__ float g_x[M_ROWS * DM];        // embeddings / layer input
__device__ float g_gx[M_ROWS * G4D];      // precomputed x-gates for current layer
__device__ float g_H0[M_ROWS * DM];       // layer-0 hidden outputs
__device__ float g_H1[M_ROWS * DM];       // layer-1 hidden outputs
__device__ float g_norm[M_ROWS * DM];     // rmsnormed
__device__ float g_hbuf[2 * BB * DM];     // double-buffered h state
__device__ unsigned int g_barrier_count;  // grid barrier ticket counter (wrap-safe)

// ---------------- Embedding gather ----------------
__global__ __launch_bounds__(256) void embed_kernel(const int* __restrict__ ids,
                                                    const float* __restrict__ emb) {
    int idx = blockIdx.x * blockDim.x + threadIdx.x;   // over M_ROWS * DM/4 float4
    int token = idx >> 8;                              // DM/4 = 256
    int d4 = idx & 255;
    int id = ids[token];
    reinterpret_cast<float4*>(g_x)[idx] =
        reinterpret_cast<const float4*>(emb + (size_t)id * DM)[d4];
}

// ---------------- SGEMM (fp32, for gate GEMMs): C = A * B^T (+bias1+bias2) ----------------
__global__ __launch_bounds__(256) void sgemm_nt_kernel(
    const float* __restrict__ A, const float* __restrict__ B,
    const float* __restrict__ bias1, const float* __restrict__ bias2,
    float* __restrict__ C, int M, int N, int K)
{
    const int BM = 128, BN = 128, BK = 8;
    __shared__ float As[BK][BM];
    __shared__ float Bs[BK][BN];
    int tid = threadIdx.x;
    int bm = blockIdx.y * BM;
    int bn = blockIdx.x * BN;

    int lrow = tid >> 1;           // 0..127
    int lk   = (tid & 1) << 2;     // 0 or 4
    const float* Ap = A + (size_t)(bm + lrow) * K + lk;
    const float* Bp = B + (size_t)(bn + lrow) * K + lk;

    int tx = tid & 15;             // n-tile 0..15
    int ty = tid >> 4;             // m-tile 0..15

    float acc[8][8];
    #pragma unroll
    for (int i = 0; i < 8; i++)
        #pragma unroll
        for (int j = 0; j < 8; j++) acc[i][j] = 0.f;

    for (int k0 = 0; k0 < K; k0 += BK) {
        float4 av = *reinterpret_cast<const float4*>(Ap + k0);
        float4 bv = *reinterpret_cast<const float4*>(Bp + k0);
        As[lk+0][lrow] = av.x; As[lk+1][lrow] = av.y;
        As[lk+2][lrow] = av.z; As[lk+3][lrow] = av.w;
        Bs[lk+0][lrow] = bv.x; Bs[lk+1][lrow] = bv.y;
        Bs[lk+2][lrow] = bv.z; Bs[lk+3][lrow] = bv.w;
        __syncthreads();
        #pragma unroll
        for (int kk = 0; kk < BK; kk++) {
            float a[8], b[8];
            *reinterpret_cast<float4*>(&a[0]) = *reinterpret_cast<const float4*>(&As[kk][ty*8]);
            *reinterpret_cast<float4*>(&a[4]) = *reinterpret_cast<const float4*>(&As[kk][ty*8+4]);
            *reinterpret_cast<float4*>(&b[0]) = *reinterpret_cast<const float4*>(&Bs[kk][tx*8]);
            *reinterpret_cast<float4*>(&b[4]) = *reinterpret_cast<const float4*>(&Bs[kk][tx*8+4]);
            #pragma unroll
            for (int i = 0; i < 8; i++)
                #pragma unroll
                for (int j = 0; j < 8; j++)
                    acc[i][j] = fmaf(a[i], b[j], acc[i][j]);
        }
        __syncthreads();
    }

    float badd[8];
    #pragma unroll
    for (int j = 0; j < 8; j++) {
        int n = bn + tx*8 + j;
        float bsum = 0.f;
        if (bias1) bsum += bias1[n];
        if (bias2) bsum += bias2[n];
        badd[j] = bsum;
    }
    #pragma unroll
    for (int i = 0; i < 8; i++) {
        float* crow = C + (size_t)(bm + ty*8 + i) * N + bn + tx*8;
        #pragma unroll
        for (int j = 0; j < 8; j += 4) {
            float4 v;
            v.x = acc[i][j+0] + badd[j+0];
            v.y = acc[i][j+1] + badd[j+1];
            v.z = acc[i][j+2] + badd[j+2];
            v.w = acc[i][j+3] + badd[j+3];
            *reinterpret_cast<float4*>(crow + j) = v;
        }
    }
}

// ---------------- TF32 tensor-core GEMM (logits): C[M,N] = A[M,K] * B[N,K]^T ----------------
// Block tile 128x256, BK=8, 256 threads = 8 warps (2x4), warp tile 64x64.
// SMEM operands stride-12 padded (conflict-free fragment LDS), cvt.rna.tf32 at store.
#define TBM 128
#define TBN 256
#define TBK 8
#define SAS 12   // floats per A row in SMEM (8 + 4 pad)
#define SBS 12

__device__ __forceinline__ uint32_t f2tf32(float x) {
    uint32_t r;
    asm("cvt.rna.tf32.f32 %0, %1;" : "=r"(r) : "f"(x));
    return r;
}
__device__ __forceinline__ uint4 cvt4_tf32(float4 v) {
    uint4 u;
    u.x = f2tf32(v.x); u.y = f2tf32(v.y); u.z = f2tf32(v.z); u.w = f2tf32(v.w);
    return u;
}
__device__ __forceinline__ void mma_tf32(float* d, const uint32_t* a, const uint32_t* b) {
    asm volatile(
        "mma.sync.aligned.m16n8k8.row.col.f32.tf32.tf32.f32 "
        "{%0,%1,%2,%3}, {%4,%5,%6,%7}, {%8,%9}, {%0,%1,%2,%3};"
        : "+f"(d[0]), "+f"(d[1]), "+f"(d[2]), "+f"(d[3])
        : "r"(a[0]), "r"(a[1]), "r"(a[2]), "r"(a[3]), "r"(b[0]), "r"(b[1]));
}

__global__ __launch_bounds__(256, 1) void mma_tf32_nt_kernel(
    const float* __restrict__ A, const float* __restrict__ B,
    float* __restrict__ C, int M, int N, int K)
{
    __shared__ __align__(16) float As[2][TBM * SAS];   // [m][k] padded, 12KB
    __shared__ __align__(16) float Bs[2][TBN * SBS];   // [n][k] padded, 24KB

    int tid = threadIdx.x, lane = tid & 31, wid = tid >> 5;
    int wm = wid & 1, wn = wid >> 1;        // warp grid 2(m) x 4(n)
    int m0 = wm * 64, n0 = wn * 64;
    int lr = lane >> 2, lc = lane & 3;      // fragment row/col within 8x4

    int bm = blockIdx.x * TBM;              // grid.x = M/128 (fast dim -> B L2 reuse)
    int bn = blockIdx.y * TBN;

    // GMEM load mapping: A 256 float4/iter (1/thread), B 512 float4/iter (2/thread)
    const float* Ag  = A + (size_t)(bm + (tid >> 1)) * K + (tid & 1) * 4;
    const float* Bg0 = B + (size_t)(bn + (tid >> 1)) * K + (tid & 1) * 4;
    const float* Bg1 = B + (size_t)(bn + 128 + (tid >> 1)) * K + (tid & 1) * 4;
    int sA = (tid >> 1) * SAS + (tid & 1) * 4;          // float offset into As
    int sB0 = (tid >> 1) * SBS + (tid & 1) * 4;
    int sB1 = (128 + (tid >> 1)) * SBS + (tid & 1) * 4;

    float acc[4][8][4];
    #pragma unroll
    for (int mf = 0; mf < 4; mf++)
        #pragma unroll
        for (int nf = 0; nf < 8; nf++)
            #pragma unroll
            for (int r = 0; r < 4; r++) acc[mf][nf][r] = 0.f;

    const int NIT = 1024 / TBK;   // K == 1024

    // prologue: load iter 0
    {
        float4 av  = *reinterpret_cast<const float4*>(Ag);
        float4 bv0 = *reinterpret_cast<const float4*>(Bg0);
        float4 bv1 = *reinterpret_cast<const float4*>(Bg1);
        *reinterpret_cast<uint4*>(&As[0][sA])  = cvt4_tf32(av);
        *reinterpret_cast<uint4*>(&Bs[0][sB0]) = cvt4_tf32(bv0);
        *reinterpret_cast<uint4*>(&Bs[0][sB1]) = cvt4_tf32(bv1);
    }
    __syncthreads();

    for (int it = 0; it < NIT; it++) {
        float4 na, nb0, nb1;
        if (it + 1 < NIT) {
            na  = *reinterpret_cast<const float4*>(Ag  + (it + 1) * TBK);
            nb0 = *reinterpret_cast<const float4*>(Bg0 + (it + 1) * TBK);
            nb1 = *reinterpret_cast<const float4*>(Bg1 + (it + 1) * TBK);
        }

        // compute on buffer it&1
        {
            const float* Asp = As[it & 1];
            const float* Bsp = Bs[it & 1];
            uint32_t afrag[4][4], bfrag[8][2];
            #pragma unroll
            for (int mf = 0; mf < 4; mf++) {
                int row = m0 + mf * 16 + lr;
                afrag[mf][0] = __float_as_uint(Asp[row * SAS + lc]);
                afrag[mf][1] = __float_as_uint(Asp[(row + 8) * SAS + lc]);
                afrag[mf][2] = __float_as_uint(Asp[row * SAS + 4 + lc]);
                afrag[mf][3] = __float_as_uint(Asp[(row + 8) * SAS + 4 + lc]);
            }
            #pragma unroll
            for (int nf = 0; nf < 8; nf++) {
                int col = n0 + nf * 8 + lr;
                bfrag[nf][0] = __float_as_uint(Bsp[col * SBS + lc]);
                bfrag[nf][1] = __float_as_uint(Bsp[col * SBS + 4 + lc]);
            }
            #pragma unroll
            for (int mf = 0; mf < 4; mf++)
                #pragma unroll
                for (int nf = 0; nf < 8; nf++)
                    mma_tf32(acc[mf][nf], afrag[mf], bfrag[nf]);
        }

        if (it + 1 < NIT) {
            int p = (it + 1) & 1;
            *reinterpret_cast<uint4*>(&As[p][sA])  = cvt4_tf32(na);
            *reinterpret_cast<uint4*>(&Bs[p][sB0]) = cvt4_tf32(nb0);
            *reinterpret_cast<uint4*>(&Bs[p][sB1]) = cvt4_tf32(nb1);
        }
        __syncthreads();
    }

    // epilogue: d0/d1 at (row, 2*lc), d2/d3 at (row+8, 2*lc)
    #pragma unroll
    for (int mf = 0; mf < 4; mf++) {
        int row = bm + m0 + mf * 16 + lr;
        #pragma unroll
        for (int nf = 0; nf < 8; nf++) {
            int col = bn + n0 + nf * 8 + lc * 2;
            float2 v0 = make_float2(acc[mf][nf][0], acc[mf][nf][1]);
            float2 v1 = make_float2(acc[mf][nf][2], acc[mf][nf][3]);
            *reinterpret_cast<float2*>(&C[(size_t)row * N + col]) = v0;
            *reinterpret_cast<float2*>(&C[(size_t)(row + 8) * N + col]) = v1;
        }
    }
}

// ---------------- Grid barrier (persistent kernel, 128 co-resident blocks) ----------------
__device__ __forceinline__ void grid_barrier() {
    __threadfence();
    __syncthreads();
    if (threadIdx.x == 0) {
        unsigned int ticket = atomicAdd(&g_barrier_count, 1);
        unsigned int target = ticket - (ticket % gridDim.x) + gridDim.x;
        volatile unsigned int* p = &g_barrier_count;
        while ((int)(*p - target) < 0) { }
    }
    __syncthreads();
}

__device__ __forceinline__ float sigmoidf_(float x) { return 1.f / (1.f + expf(-x)); }

// ---------------- LSTM layer (persistent; Wh register-resident) ----------------
#define LSTM_BLOCKS 128
#define LSTM_THREADS 512

__global__ __launch_bounds__(LSTM_THREADS, 1) void lstm_layer_kernel(
    const float* __restrict__ Gx, const float* __restrict__ Wh,
    float* __restrict__ H, float* __restrict__ hn, float* __restrict__ cn)
{
    __shared__ float4 sh4[BB * 256];       // h_prev: [b][k4], 32KB (broadcast reads)
    __shared__ float  sred[16 * 288];      // partials: [w][lane*9 + b], stride-9 pad
    __shared__ float  sgate[256];          // gates: [r][b]

    int tid  = threadIdx.x;
    int w    = tid >> 5;                   // warp id = k-slice 0..15
    int lane = tid & 31;                   // lane = row 0..31
    int chunk = lane >> 3, dl = lane & 7;
    int d    = blockIdx.x * 8 + dl;
    int grow = chunk * DM + d;

    float4 wreg[16];
    {
        const float4* wrow = reinterpret_cast<const float4*>(Wh + (size_t)grow * DM) + w * 16;
        #pragma unroll
        for (int i = 0; i < 16; i++) wreg[i] = wrow[i];
    }

    int rr = tid >> 3, bb = tid & 7;
    int grow_red = (rr >> 3) * DM + blockIdx.x * 8 + (rr & 7);

    float c_state = 0.f;
    int a_dl = tid >> 3, a_b = tid & 7;
    int a_d  = blockIdx.x * 8 + a_dl;

    for (int t = 0; t < SS; t++) {
        if (t > 0) {
            const float4* hb4 = reinterpret_cast<const float4*>(g_hbuf + ((t-1)&1) * (BB*DM));
            #pragma unroll
            for (int i = tid; i < BB * 256; i += LSTM_THREADS)
                sh4[i] = __ldcg(hb4 + i);
        }
        __syncthreads();

        float gx = 0.f;
        if (tid < 256)
            gx = __ldg(Gx + (size_t)(bb * SS + t) * G4D + grow_red);

        float acc[8];
        #pragma unroll
        for (int b = 0; b < 8; b++) acc[b] = 0.f;
        if (t > 0) {
            const float4* shw = &sh4[w * 16];
            #pragma unroll
            for (int k4 = 0; k4 < 16; k4++) {
                float4 wv = wreg[k4];
                #pragma unroll
                for (int b = 0; b < 8; b++) {
                    float4 h = shw[b * 256 + k4];
                    acc[b] = fmaf(wv.x, h.x, acc[b]);
                    acc[b] = fmaf(wv.y, h.y, acc[b]);
                    acc[b] = fmaf(wv.z, h.z, acc[b]);
                    acc[b] = fmaf(wv.w, h.w, acc[b]);
                }
            }
        }

        float* pr = &sred[(w * 32 + lane) * 9];
        #pragma unroll
        for (int b = 0; b < 8; b++) pr[b] = acc[b];
        __syncthreads();

        if (tid < 256) {
            float s = gx;
            #pragma unroll
            for (int ww = 0; ww < 16; ww++)
                s += sred[ww * 288 + rr * 9 + bb];
            sgate[rr * 8 + bb] = s;
        }
        __syncthreads();

        if (tid < 64) {
            float gi = sgate[(0  + a_dl) * 8 + a_b];
            float gf = sgate[(8  + a_dl) * 8 + a_b];
            float go = sgate[(16 + a_dl) * 8 + a_b];
            float gg = sgate[(24 + a_dl) * 8 + a_b];
            float i_s = sigmoidf_(gi);
            float f_s = sigmoidf_(gf);
            float o_s = sigmoidf_(go);
            c_state = f_s * c_state + i_s * tanhf(gg);
            float h_new = o_s * tanhf(c_state);
            H[((size_t)(a_b * SS + t)) * DM + a_d] = h_new;
            g_hbuf[(t & 1) * (BB * DM) + a_b * DM + a_d] = h_new;
            if (t == SS - 1) {
                hn[a_b * DM + a_d] = h_new;
                cn[a_b * DM + a_d] = c_state;
            }
        }
        grid_barrier();
    }
}

// ---------------- RMSNorm (one block per row) ----------------
__global__ __launch_bounds__(256) void rmsnorm_kernel(const float* __restrict__ in,
                                                      const float* __restrict__ w) {
    int row = blockIdx.x;
    int tid = threadIdx.x;
    const float4* r4 = reinterpret_cast<const float4*>(in + (size_t)row * DM);
    float4 v = r4[tid];
    float s = v.x*v.x + v.y*v.y + v.z*v.z + v.w*v.w;
    #pragma unroll
    for (int o = 16; o; o >>= 1) s += __shfl_xor_sync(0xFFFFFFFFu, s, o);
    __shared__ float red[8];
    if ((tid & 31) == 0) red[tid >> 5] = s;
    __syncthreads();
    float tot = red[0]+red[1]+red[2]+red[3]+red[4]+red[5]+red[6]+red[7];
    float scale = rsqrtf(tot * (1.f/ (float)DM) + 1e-5f);
    float4 wv = reinterpret_cast<const float4*>(w)[tid];
    float4 o4;
    o4.x = v.x * scale * wv.x;
    o4.y = v.y * scale * wv.y;
    o4.z = v.z * scale * wv.z;
    o4.w = v.w * scale * wv.w;
    reinterpret_cast<float4*>(g_norm + (size_t)row * DM)[tid] = o4;
}

// ---------------- Launch ----------------
extern "C" void kernel_launch(void* const* d_in, const int* in_sizes, int n_in,
                              void* d_out, int out_size) {
    const int*   ids = (const int*)d_in[0];
    const float* emb = (const float*)d_in[1];
    const float* Wx  = (const float*)d_in[2];
    const float* bx  = (const float*)d_in[3];
    const float* Wh  = (const float*)d_in[4];
    const float* bh  = (const float*)d_in[5];
    const float* nw  = (const float*)d_in[6];
    const float* ow  = (const float*)d_in[7];

    float* out = (float*)d_out;
    float* logits = out;
    float* hn = out + (size_t)M_ROWS * VOCAB;   // [L,B,D]
    float* cn = hn + (size_t)NL * BB * DM;      // [L,B,D]

    float *px, *pgx, *pH0, *pH1, *pnorm;
    cudaGetSymbolAddress((void**)&px,    g_x);
    cudaGetSymbolAddress((void**)&pgx,   g_gx);
    cudaGetSymbolAddress((void**)&pH0,   g_H0);
    cudaGetSymbolAddress((void**)&pH1,   g_H1);
    cudaGetSymbolAddress((void**)&pnorm, g_norm);

    // 1. embeddings
    embed_kernel<<<M_ROWS * (DM/4) / 256, 256>>>(ids, emb);

    // 2. layer 0 x-gates (fp32)
    sgemm_nt_kernel<<<dim3(G4D/128, M_ROWS/128), 256>>>(
        px, Wx, bx, bh, pgx, M_ROWS, G4D, DM);

    // 3. layer 0 recurrence
    lstm_layer_kernel<<<LSTM_BLOCKS, LSTM_THREADS>>>(pgx, Wh, pH0, hn, cn);

    // 4. layer 1 x-gates (fp32)
    sgemm_nt_kernel<<<dim3(G4D/128, M_ROWS/128), 256>>>(
        pH0, Wx + (size_t)G4D*DM, bx + G4D, bh + G4D, pgx, M_ROWS, G4D, DM);

    // 5. layer 1 recurrence
    lstm_layer_kernel<<<LSTM_BLOCKS, LSTM_THREADS>>>(pgx, Wh + (size_t)G4D*DM, pH1,
                                                     hn + BB*DM, cn + BB*DM);

    // 6. RMSNorm
    rmsnorm_kernel<<<M_ROWS, 256>>>(pH1, nw);

    // 7. logits (tf32 tensor cores): [2048,1024] x [32000,1024]^T
    mma_tf32_nt_kernel<<<dim3(M_ROWS/TBM, VOCAB/TBN), 256>>>(
        pnorm, ow, logits, M_ROWS, VOCAB, DM);
}

// round 9
// speedup vs baseline: 4.1230x; 1.0458x over previous
#include <cuda_runtime.h>
#include <cuda_bf16.h>
#include <math.h>
#include <stdint.h>

// ---------------- Problem constants ----------------
#define VOCAB 32000
#define DM    1024
#define NL    2
#define BB    8
#define SS    256
#define M_ROWS (BB*SS)          // 2048
#define G4D   (4*DM)            // 4096

// ---------------- Scratch (static device globals; no allocation) ----------------
__device__ float g_x[M_ROWS * DM];        // embeddings / layer input
__device__ float g_gx[M_ROWS * G4D];      // precomputed x-gates for current layer
__device__ float g_H0[M_ROWS * DM];       // layer-0 hidden outputs
__device__ float g_H1[M_ROWS * DM];       // layer-1 hidden outputs
__device__ float g_norm[M_ROWS * DM];     // rmsnormed (tf32-rounded values)
__device__ float g_owt[(size_t)VOCAB * DM]; // out_weight, tf32-rounded copy
__device__ float g_hbuf[2 * BB * DM];     // double-buffered h state
__device__ unsigned int g_barrier_count;  // grid barrier ticket counter (wrap-safe)

// ---------------- tf32 helpers ----------------
__device__ __forceinline__ uint32_t f2tf32(float x) {
    uint32_t r;
    asm("cvt.rna.tf32.f32 %0, %1;" : "=r"(r) : "f"(x));
    return r;   // f32 bit layout, low 13 mantissa bits zeroed
}
__device__ __forceinline__ void mma_tf32(float* d, const uint32_t* a, const uint32_t* b) {
    asm volatile(
        "mma.sync.aligned.m16n8k8.row.col.f32.tf32.tf32.f32 "
        "{%0,%1,%2,%3}, {%4,%5,%6,%7}, {%8,%9}, {%0,%1,%2,%3};"
        : "+f"(d[0]), "+f"(d[1]), "+f"(d[2]), "+f"(d[3])
        : "r"(a[0]), "r"(a[1]), "r"(a[2]), "r"(a[3]), "r"(b[0]), "r"(b[1]));
}
__device__ __forceinline__ void cpasync16(uint32_t saddr, const void* g) {
    asm volatile("cp.async.cg.shared.global [%0], [%1], 16;" :: "r"(saddr), "l"(g));
}

// ---------------- Embedding gather ----------------
__global__ __launch_bounds__(256) void embed_kernel(const int* __restrict__ ids,
                                                    const float* __restrict__ emb) {
    int idx = blockIdx.x * blockDim.x + threadIdx.x;
    int token = idx >> 8;                              // DM/4 = 256
    int d4 = idx & 255;
    int id = ids[token];
    reinterpret_cast<float4*>(g_x)[idx] =
        reinterpret_cast<const float4*>(emb + (size_t)id * DM)[d4];
}

// ---------------- Pre-round out_weight to tf32 format ----------------
__global__ __launch_bounds__(256) void round_tf32_kernel(const float* __restrict__ in,
                                                         float* __restrict__ out) {
    size_t idx = (size_t)blockIdx.x * blockDim.x + threadIdx.x;   // over float4 elems
    float4 v = reinterpret_cast<const float4*>(in)[idx];
    float4 o;
    o.x = __uint_as_float(f2tf32(v.x));
    o.y = __uint_as_float(f2tf32(v.y));
    o.z = __uint_as_float(f2tf32(v.z));
    o.w = __uint_as_float(f2tf32(v.w));
    reinterpret_cast<float4*>(out)[idx] = o;
}

// ---------------- SGEMM (fp32, for gate GEMMs): C = A * B^T (+bias1+bias2) ----------------
__global__ __launch_bounds__(256) void sgemm_nt_kernel(
    const float* __restrict__ A, const float* __restrict__ B,
    const float* __restrict__ bias1, const float* __restrict__ bias2,
    float* __restrict__ C, int M, int N, int K)
{
    const int BM = 128, BN = 128, BK = 8;
    __shared__ float As[BK][BM];
    __shared__ float Bs[BK][BN];
    int tid = threadIdx.x;
    int bm = blockIdx.y * BM;
    int bn = blockIdx.x * BN;

    int lrow = tid >> 1;
    int lk   = (tid & 1) << 2;
    const float* Ap = A + (size_t)(bm + lrow) * K + lk;
    const float* Bp = B + (size_t)(bn + lrow) * K + lk;

    int tx = tid & 15;
    int ty = tid >> 4;

    float acc[8][8];
    #pragma unroll
    for (int i = 0; i < 8; i++)
        #pragma unroll
        for (int j = 0; j < 8; j++) acc[i][j] = 0.f;

    for (int k0 = 0; k0 < K; k0 += BK) {
        float4 av = *reinterpret_cast<const float4*>(Ap + k0);
        float4 bv = *reinterpret_cast<const float4*>(Bp + k0);
        As[lk+0][lrow] = av.x; As[lk+1][lrow] = av.y;
        As[lk+2][lrow] = av.z; As[lk+3][lrow] = av.w;
        Bs[lk+0][lrow] = bv.x; Bs[lk+1][lrow] = bv.y;
        Bs[lk+2][lrow] = bv.z; Bs[lk+3][lrow] = bv.w;
        __syncthreads();
        #pragma unroll
        for (int kk = 0; kk < BK; kk++) {
            float a[8], b[8];
            *reinterpret_cast<float4*>(&a[0]) = *reinterpret_cast<const float4*>(&As[kk][ty*8]);
            *reinterpret_cast<float4*>(&a[4]) = *reinterpret_cast<const float4*>(&As[kk][ty*8+4]);
            *reinterpret_cast<float4*>(&b[0]) = *reinterpret_cast<const float4*>(&Bs[kk][tx*8]);
            *reinterpret_cast<float4*>(&b[4]) = *reinterpret_cast<const float4*>(&Bs[kk][tx*8+4]);
            #pragma unroll
            for (int i = 0; i < 8; i++)
                #pragma unroll
                for (int j = 0; j < 8; j++)
                    acc[i][j] = fmaf(a[i], b[j], acc[i][j]);
        }
        __syncthreads();
    }

    float badd[8];
    #pragma unroll
    for (int j = 0; j < 8; j++) {
        int n = bn + tx*8 + j;
        float bsum = 0.f;
        if (bias1) bsum += bias1[n];
        if (bias2) bsum += bias2[n];
        badd[j] = bsum;
    }
    #pragma unroll
    for (int i = 0; i < 8; i++) {
        float* crow = C + (size_t)(bm + ty*8 + i) * N + bn + tx*8;
        #pragma unroll
        for (int j = 0; j < 8; j += 4) {
            float4 v;
            v.x = acc[i][j+0] + badd[j+0];
            v.y = acc[i][j+1] + badd[j+1];
            v.z = acc[i][j+2] + badd[j+2];
            v.w = acc[i][j+3] + badd[j+3];
            *reinterpret_cast<float4*>(crow + j) = v;
        }
    }
}

// ---------------- Pipelined TF32 GEMM (logits): C[M,N] = A[M,K] * B[N,K]^T ----------------
// Operands MUST be pre-rounded to tf32 format (f32 layout, low 13 bits zero).
// Block 128x256, BK=16, 3-stage cp.async, 8 warps (2m x 4n), warp tile 64x64.
// SMEM row stride 20 floats: conflict-free fragment LDS, 16B-aligned for cp.async.
#define PBM 128
#define PBN 256
#define PBK 16
#define PSTR 20
#define PSTAGES 3
#define PASTG (PBM*PSTR)
#define PBSTG (PBN*PSTR)
#define PSMEM_BYTES (PSTAGES*(PASTG+PBSTG)*4)   // 92160

__global__ __launch_bounds__(256, 1) void mma_tf32_pipe_kernel(
    const float* __restrict__ A, const float* __restrict__ B,
    float* __restrict__ C, int M, int N, int K)
{
    extern __shared__ float smem[];
    float* As = smem;                       // [PSTAGES][PASTG]
    float* Bs = smem + PSTAGES * PASTG;     // [PSTAGES][PBSTG]

    int tid = threadIdx.x, lane = tid & 31, wid = tid >> 5;
    int wm = wid & 1, wn = wid >> 1;
    int m0 = wm * 64, n0 = wn * 64;
    int lr = lane >> 2, lc = lane & 3;

    int bm = blockIdx.x * PBM;
    int bn = blockIdx.y * PBN;

    // cp.async mappings (chunk = 16B = 4 floats; 4 chunks per row of 16 k)
    int arow0 = tid >> 2, akc = tid & 3;          // A chunks: tid, tid+256
    const float* Ag0 = A + (size_t)(bm + arow0) * K + akc * 4;
    const float* Ag1 = A + (size_t)(bm + arow0 + 64) * K + akc * 4;
    uint32_t sA0 = (uint32_t)__cvta_generic_to_shared(As + arow0 * PSTR + akc * 4);
    uint32_t sA1 = (uint32_t)__cvta_generic_to_shared(As + (arow0 + 64) * PSTR + akc * 4);
    const float* Bg0 = B + (size_t)(bn + arow0) * K + akc * 4;   // B chunks: tid + 256*j
    const float* Bg1 = B + (size_t)(bn + arow0 + 64) * K + akc * 4;
    const float* Bg2 = B + (size_t)(bn + arow0 + 128) * K + akc * 4;
    const float* Bg3 = B + (size_t)(bn + arow0 + 192) * K + akc * 4;
    uint32_t sB0 = (uint32_t)__cvta_generic_to_shared(Bs + arow0 * PSTR + akc * 4);

    float acc[4][8][4];
    #pragma unroll
    for (int mf = 0; mf < 4; mf++)
        #pragma unroll
        for (int nf = 0; nf < 8; nf++)
            #pragma unroll
            for (int r = 0; r < 4; r++) acc[mf][nf][r] = 0.f;

    const int NIT = K / PBK;   // 64

    // stage loader
    auto load_stage = [&](int s, int kt) {
        uint32_t aoff = s * PASTG * 4;
        uint32_t boff = s * PBSTG * 4;
        int g = kt * PBK;
        cpasync16(sA0 + aoff, Ag0 + g);
        cpasync16(sA1 + aoff, Ag1 + g);
        cpasync16(sB0 + boff,                  Bg0 + g);
        cpasync16(sB0 + boff + 64*PSTR*4,      Bg1 + g);
        cpasync16(sB0 + boff + 128*PSTR*4,     Bg2 + g);
        cpasync16(sB0 + boff + 192*PSTR*4,     Bg3 + g);
    };

    load_stage(0, 0);
    asm volatile("cp.async.commit_group;");
    load_stage(1, 1);
    asm volatile("cp.async.commit_group;");

    int s = 0;
    for (int kt = 0; kt < NIT; kt++) {
        asm volatile("cp.async.wait_group 1;");
        __syncthreads();
        if (kt + 2 < NIT) load_stage((kt + 2) % PSTAGES, kt + 2);
        asm volatile("cp.async.commit_group;");

        const float* Asp = As + s * PASTG;
        const float* Bsp = Bs + s * PBSTG;
        #pragma unroll
        for (int ks = 0; ks < 2; ks++) {
            int k0 = ks * 8;
            uint32_t af[4][4], bf[8][2];
            #pragma unroll
            for (int mf = 0; mf < 4; mf++) {
                int row = m0 + mf * 16 + lr;
                af[mf][0] = __float_as_uint(Asp[row * PSTR + k0 + lc]);
                af[mf][1] = __float_as_uint(Asp[(row + 8) * PSTR + k0 + lc]);
                af[mf][2] = __float_as_uint(Asp[row * PSTR + k0 + 4 + lc]);
                af[mf][3] = __float_as_uint(Asp[(row + 8) * PSTR + k0 + 4 + lc]);
            }
            #pragma unroll
            for (int nf = 0; nf < 8; nf++) {
                int col = n0 + nf * 8 + lr;
                bf[nf][0] = __float_as_uint(Bsp[col * PSTR + k0 + lc]);
                bf[nf][1] = __float_as_uint(Bsp[col * PSTR + k0 + 4 + lc]);
            }
            #pragma unroll
            for (int mf = 0; mf < 4; mf++)
                #pragma unroll
                for (int nf = 0; nf < 8; nf++)
                    mma_tf32(acc[mf][nf], af[mf], bf[nf]);
        }
        s++; if (s == PSTAGES) s = 0;
    }

    #pragma unroll
    for (int mf = 0; mf < 4; mf++) {
        int row = bm + m0 + mf * 16 + lr;
        #pragma unroll
        for (int nf = 0; nf < 8; nf++) {
            int col = bn + n0 + nf * 8 + lc * 2;
            float2 v0 = make_float2(acc[mf][nf][0], acc[mf][nf][1]);
            float2 v1 = make_float2(acc[mf][nf][2], acc[mf][nf][3]);
            *reinterpret_cast<float2*>(&C[(size_t)row * N + col]) = v0;
            *reinterpret_cast<float2*>(&C[(size_t)(row + 8) * N + col]) = v1;
        }
    }
}

// ---------------- Grid barrier (persistent kernel, 128 co-resident blocks) ----------------
__device__ __forceinline__ void grid_barrier() {
    __threadfence();
    __syncthreads();
    if (threadIdx.x == 0) {
        unsigned int ticket = atomicAdd(&g_barrier_count, 1);
        unsigned int target = ticket - (ticket % gridDim.x) + gridDim.x;
        volatile unsigned int* p = &g_barrier_count;
        while ((int)(*p - target) < 0) { }
    }
    __syncthreads();
}

__device__ __forceinline__ float sigmoidf_(float x) { return 1.f / (1.f + expf(-x)); }

// ---------------- LSTM layer (persistent; Wh register-resident) ----------------
#define LSTM_BLOCKS 128
#define LSTM_THREADS 512

__global__ __launch_bounds__(LSTM_THREADS, 1) void lstm_layer_kernel(
    const float* __restrict__ Gx, const float* __restrict__ Wh,
    float* __restrict__ H, float* __restrict__ hn, float* __restrict__ cn)
{
    __shared__ float4 sh4[BB * 256];
    __shared__ float  sred[16 * 288];
    __shared__ float  sgate[256];

    int tid  = threadIdx.x;
    int w    = tid >> 5;
    int lane = tid & 31;
    int chunk = lane >> 3, dl = lane & 7;
    int d    = blockIdx.x * 8 + dl;
    int grow = chunk * DM + d;

    float4 wreg[16];
    {
        const float4* wrow = reinterpret_cast<const float4*>(Wh + (size_t)grow * DM) + w * 16;
        #pragma unroll
        for (int i = 0; i < 16; i++) wreg[i] = wrow[i];
    }

    int rr = tid >> 3, bb = tid & 7;
    int grow_red = (rr >> 3) * DM + blockIdx.x * 8 + (rr & 7);

    float c_state = 0.f;
    int a_dl = tid >> 3, a_b = tid & 7;
    int a_d  = blockIdx.x * 8 + a_dl;

    for (int t = 0; t < SS; t++) {
        if (t > 0) {
            const float4* hb4 = reinterpret_cast<const float4*>(g_hbuf + ((t-1)&1) * (BB*DM));
            #pragma unroll
            for (int i = tid; i < BB * 256; i += LSTM_THREADS)
                sh4[i] = __ldcg(hb4 + i);
        }
        __syncthreads();

        float gx = 0.f;
        if (tid < 256)
            gx = __ldg(Gx + (size_t)(bb * SS + t) * G4D + grow_red);

        float acc[8];
        #pragma unroll
        for (int b = 0; b < 8; b++) acc[b] = 0.f;
        if (t > 0) {
            const float4* shw = &sh4[w * 16];
            #pragma unroll
            for (int k4 = 0; k4 < 16; k4++) {
                float4 wv = wreg[k4];
                #pragma unroll
                for (int b = 0; b < 8; b++) {
                    float4 h = shw[b * 256 + k4];
                    acc[b] = fmaf(wv.x, h.x, acc[b]);
                    acc[b] = fmaf(wv.y, h.y, acc[b]);
                    acc[b] = fmaf(wv.z, h.z, acc[b]);
                    acc[b] = fmaf(wv.w, h.w, acc[b]);
                }
            }
        }

        float* pr = &sred[(w * 32 + lane) * 9];
        #pragma unroll
        for (int b = 0; b < 8; b++) pr[b] = acc[b];
        __syncthreads();

        if (tid < 256) {
            float sgx = gx;
            #pragma unroll
            for (int ww = 0; ww < 16; ww++)
                sgx += sred[ww * 288 + rr * 9 + bb];
            sgate[rr * 8 + bb] = sgx;
        }
        __syncthreads();

        if (tid < 64) {
            float gi = sgate[(0  + a_dl) * 8 + a_b];
            float gf = sgate[(8  + a_dl) * 8 + a_b];
            float go = sgate[(16 + a_dl) * 8 + a_b];
            float gg = sgate[(24 + a_dl) * 8 + a_b];
            float i_s = sigmoidf_(gi);
            float f_s = sigmoidf_(gf);
            float o_s = sigmoidf_(go);
            c_state = f_s * c_state + i_s * tanhf(gg);
            float h_new = o_s * tanhf(c_state);
            H[((size_t)(a_b * SS + t)) * DM + a_d] = h_new;
            g_hbuf[(t & 1) * (BB * DM) + a_b * DM + a_d] = h_new;
            if (t == SS - 1) {
                hn[a_b * DM + a_d] = h_new;
                cn[a_b * DM + a_d] = c_state;
            }
        }
        grid_barrier();
    }
}

// ---------------- RMSNorm (one block per row; emits tf32-rounded values) ----------------
__global__ __launch_bounds__(256) void rmsnorm_kernel(const float* __restrict__ in,
                                                      const float* __restrict__ w) {
    int row = blockIdx.x;
    int tid = threadIdx.x;
    const float4* r4 = reinterpret_cast<const float4*>(in + (size_t)row * DM);
    float4 v = r4[tid];
    float s = v.x*v.x + v.y*v.y + v.z*v.z + v.w*v.w;
    #pragma unroll
    for (int o = 16; o; o >>= 1) s += __shfl_xor_sync(0xFFFFFFFFu, s, o);
    __shared__ float red[8];
    if ((tid & 31) == 0) red[tid >> 5] = s;
    __syncthreads();
    float tot = red[0]+red[1]+red[2]+red[3]+red[4]+red[5]+red[6]+red[7];
    float scale = rsqrtf(tot * (1.f/ (float)DM) + 1e-5f);
    float4 wv = reinterpret_cast<const float4*>(w)[tid];
    float4 o4;
    o4.x = __uint_as_float(f2tf32(v.x * scale * wv.x));
    o4.y = __uint_as_float(f2tf32(v.y * scale * wv.y));
    o4.z = __uint_as_float(f2tf32(v.z * scale * wv.z));
    o4.w = __uint_as_float(f2tf32(v.w * scale * wv.w));
    reinterpret_cast<float4*>(g_norm + (size_t)row * DM)[tid] = o4;
}

// ---------------- Launch ----------------
extern "C" void kernel_launch(void* const* d_in, const int* in_sizes, int n_in,
                              void* d_out, int out_size) {
    const int*   ids = (const int*)d_in[0];
    const float* emb = (const float*)d_in[1];
    const float* Wx  = (const float*)d_in[2];
    const float* bx  = (const float*)d_in[3];
    const float* Wh  = (const float*)d_in[4];
    const float* bh  = (const float*)d_in[5];
    const float* nw  = (const float*)d_in[6];
    const float* ow  = (const float*)d_in[7];

    float* out = (float*)d_out;
    float* logits = out;
    float* hn = out + (size_t)M_ROWS * VOCAB;
    float* cn = hn + (size_t)NL * BB * DM;

    float *px, *pgx, *pH0, *pH1, *pnorm, *powt;
    cudaGetSymbolAddress((void**)&px,    g_x);
    cudaGetSymbolAddress((void**)&pgx,   g_gx);
    cudaGetSymbolAddress((void**)&pH0,   g_H0);
    cudaGetSymbolAddress((void**)&pH1,   g_H1);
    cudaGetSymbolAddress((void**)&pnorm, g_norm);
    cudaGetSymbolAddress((void**)&powt,  g_owt);

    static bool attr_done = false;
    if (!attr_done) {
        cudaFuncSetAttribute(mma_tf32_pipe_kernel,
                             cudaFuncAttributeMaxDynamicSharedMemorySize, PSMEM_BYTES);
        attr_done = true;
    }

    // 0. pre-round out_weight to tf32 (independent of everything else)
    round_tf32_kernel<<<(VOCAB/4) * (DM/256), 256>>>(ow, powt);

    // 1. embeddings
    embed_kernel<<<M_ROWS * (DM/4) / 256, 256>>>(ids, emb);

    // 2. layer 0 x-gates (fp32)
    sgemm_nt_kernel<<<dim3(G4D/128, M_ROWS/128), 256>>>(
        px, Wx, bx, bh, pgx, M_ROWS, G4D, DM);

    // 3. layer 0 recurrence
    lstm_layer_kernel<<<LSTM_BLOCKS, LSTM_THREADS>>>(pgx, Wh, pH0, hn, cn);

    // 4. layer 1 x-gates (fp32)
    sgemm_nt_kernel<<<dim3(G4D/128, M_ROWS/128), 256>>>(
        pH0, Wx + (size_t)G4D*DM, bx + G4D, bh + G4D, pgx, M_ROWS, G4D, DM);

    // 5. layer 1 recurrence
    lstm_layer_kernel<<<LSTM_BLOCKS, LSTM_THREADS>>>(pgx, Wh + (size_t)G4D*DM, pH1,
                                                     hn + BB*DM, cn + BB*DM);

    // 6. RMSNorm (tf32-rounded output)
    rmsnorm_kernel<<<M_ROWS, 256>>>(pH1, nw);

    // 7. logits (pipelined tf32 tensor cores)
    mma_tf32_pipe_kernel<<<dim3(M_ROWS/PBM, VOCAB/PBN), 256, PSMEM_BYTES>>>(
        pnorm, powt, logits, M_ROWS, VOCAB, DM);
}

// round 11
// speedup vs baseline: 4.1798x; 1.0138x over previous
#include <cuda_runtime.h>
#include <cuda_bf16.h>
#include <math.h>
#include <stdint.h>

// ---------------- Problem constants ----------------
#define VOCAB 32000
#define DM    1024
#define NL    2
#define BB    8
#define SS    256
#define M_ROWS (BB*SS)          // 2048
#define G4D   (4*DM)            // 4096

// ---------------- Scratch (static device globals; no allocation) ----------------
__device__ float g_x[M_ROWS * DM];        // embeddings / layer input
__device__ float g_gx[M_ROWS * G4D];      // precomputed x-gates for current layer
__device__ float g_H0[M_ROWS * DM];       // layer-0 hidden outputs
__device__ float g_H1[M_ROWS * DM];       // layer-1 hidden outputs
__device__ float g_norm[M_ROWS * DM];     // rmsnormed (tf32-rounded values)
__device__ float g_owt[(size_t)VOCAB * DM]; // out_weight, tf32-rounded copy
__device__ float g_hbuf[2 * BB * DM];     // double-buffered h state, layout [k][b]
__device__ unsigned int g_barrier_count;  // grid barrier ticket counter (wrap-safe)

// ---------------- tf32 / packed-f32x2 helpers ----------------
__device__ __forceinline__ uint32_t f2tf32(float x) {
    uint32_t r;
    asm("cvt.rna.tf32.f32 %0, %1;" : "=r"(r) : "f"(x));
    return r;   // f32 bit layout, low 13 mantissa bits zeroed
}
__device__ __forceinline__ void mma_tf32(float* d, const uint32_t* a, const uint32_t* b) {
    asm volatile(
        "mma.sync.aligned.m16n8k8.row.col.f32.tf32.tf32.f32 "
        "{%0,%1,%2,%3}, {%4,%5,%6,%7}, {%8,%9}, {%0,%1,%2,%3};"
        : "+f"(d[0]), "+f"(d[1]), "+f"(d[2]), "+f"(d[3])
        : "r"(a[0]), "r"(a[1]), "r"(a[2]), "r"(a[3]), "r"(b[0]), "r"(b[1]));
}
__device__ __forceinline__ void cpasync16(uint32_t saddr, const void* g) {
    asm volatile("cp.async.cg.shared.global [%0], [%1], 16;" :: "r"(saddr), "l"(g));
}
// FFMA2: two independent fp32 FMAs (rn) per instruction — same rounding as fmaf.
__device__ __forceinline__ void ffma2(unsigned long long& d, unsigned long long a,
                                      unsigned long long b) {
    asm("fma.rn.f32x2 %0, %1, %2, %0;" : "+l"(d) : "l"(a), "l"(b));
}
__device__ __forceinline__ unsigned long long pack2(float x) {
    unsigned long long r;
    uint32_t u = __float_as_uint(x);
    asm("mov.b64 %0, {%1, %1};" : "=l"(r) : "r"(u));
    return r;
}
__device__ __forceinline__ void unpack2(unsigned long long v, float& lo, float& hi) {
    uint32_t a, b;
    asm("mov.b64 {%0, %1}, %2;" : "=r"(a), "=r"(b) : "l"(v));
    lo = __uint_as_float(a); hi = __uint_as_float(b);
}

// ---------------- Embedding gather ----------------
__global__ __launch_bounds__(256) void embed_kernel(const int* __restrict__ ids,
                                                    const float* __restrict__ emb) {
    int idx = blockIdx.x * blockDim.x + threadIdx.x;
    int token = idx >> 8;                              // DM/4 = 256
    int d4 = idx & 255;
    int id = ids[token];
    reinterpret_cast<float4*>(g_x)[idx] =
        reinterpret_cast<const float4*>(emb + (size_t)id * DM)[d4];
}

// ---------------- Pre-round out_weight to tf32 format ----------------
__global__ __launch_bounds__(256) void round_tf32_kernel(const float* __restrict__ in,
                                                         float* __restrict__ out) {
    size_t idx = (size_t)blockIdx.x * blockDim.x + threadIdx.x;   // over float4 elems
    float4 v = reinterpret_cast<const float4*>(in)[idx];
    float4 o;
    o.x = __uint_as_float(f2tf32(v.x));
    o.y = __uint_as_float(f2tf32(v.y));
    o.z = __uint_as_float(f2tf32(v.z));
    o.w = __uint_as_float(f2tf32(v.w));
    reinterpret_cast<float4*>(out)[idx] = o;
}

// ---------------- SGEMM (fp32 via FFMA2, gate GEMMs): C = A*B^T (+bias1+bias2) ----------
__global__ __launch_bounds__(256) void sgemm_nt_kernel(
    const float* __restrict__ A, const float* __restrict__ B,
    const float* __restrict__ bias1, const float* __restrict__ bias2,
    float* __restrict__ C, int M, int N, int K)
{
    const int BM = 128, BN = 128, BK = 8;
    __shared__ float As[BK][BM];
    __shared__ __align__(16) float Bs[BK][BN];
    int tid = threadIdx.x;
    int bm = blockIdx.y * BM;
    int bn = blockIdx.x * BN;

    int lrow = tid >> 1;
    int lk   = (tid & 1) << 2;
    const float* Ap = A + (size_t)(bm + lrow) * K + lk;
    const float* Bp = B + (size_t)(bn + lrow) * K + lk;

    int tx = tid & 15;
    int ty = tid >> 4;

    unsigned long long acc2[8][4];   // [i][jpair]: {c(j*2), c(j*2+1)}
    #pragma unroll
    for (int i = 0; i < 8; i++)
        #pragma unroll
        for (int j = 0; j < 4; j++) acc2[i][j] = 0ull;

    for (int k0 = 0; k0 < K; k0 += BK) {
        float4 av = *reinterpret_cast<const float4*>(Ap + k0);
        float4 bv = *reinterpret_cast<const float4*>(Bp + k0);
        As[lk+0][lrow] = av.x; As[lk+1][lrow] = av.y;
        As[lk+2][lrow] = av.z; As[lk+3][lrow] = av.w;
        Bs[lk+0][lrow] = bv.x; Bs[lk+1][lrow] = bv.y;
        Bs[lk+2][lrow] = bv.z; Bs[lk+3][lrow] = bv.w;
        __syncthreads();
        #pragma unroll
        for (int kk = 0; kk < BK; kk++) {
            float a[8];
            *reinterpret_cast<float4*>(&a[0]) = *reinterpret_cast<const float4*>(&As[kk][ty*8]);
            *reinterpret_cast<float4*>(&a[4]) = *reinterpret_cast<const float4*>(&As[kk][ty*8+4]);
            const ulonglong2* bp2 = reinterpret_cast<const ulonglong2*>(&Bs[kk][tx*8]);
            ulonglong2 b03 = bp2[0];
            ulonglong2 b47 = bp2[1];
            #pragma unroll
            for (int i = 0; i < 8; i++) {
                unsigned long long ap = pack2(a[i]);
                ffma2(acc2[i][0], ap, b03.x);
                ffma2(acc2[i][1], ap, b03.y);
                ffma2(acc2[i][2], ap, b47.x);
                ffma2(acc2[i][3], ap, b47.y);
            }
        }
        __syncthreads();
    }

    float badd[8];
    #pragma unroll
    for (int j = 0; j < 8; j++) {
        int n = bn + tx*8 + j;
        float bsum = 0.f;
        if (bias1) bsum += bias1[n];
        if (bias2) bsum += bias2[n];
        badd[j] = bsum;
    }
    #pragma unroll
    for (int i = 0; i < 8; i++) {
        float c[8];
        #pragma unroll
        for (int j = 0; j < 4; j++) unpack2(acc2[i][j], c[j*2], c[j*2+1]);
        float* crow = C + (size_t)(bm + ty*8 + i) * N + bn + tx*8;
        #pragma unroll
        for (int j = 0; j < 8; j += 4) {
            float4 v;
            v.x = c[j+0] + badd[j+0];
            v.y = c[j+1] + badd[j+1];
            v.z = c[j+2] + badd[j+2];
            v.w = c[j+3] + badd[j+3];
            *reinterpret_cast<float4*>(crow + j) = v;
        }
    }
}

// ---------------- Pipelined TF32 GEMM (logits): C[M,N] = A[M,K] * B[N,K]^T ----------------
// Operands pre-rounded to tf32 (f32 layout). Block 128x256, BK=16, 3-stage cp.async,
// 8 warps (2m x 4n), warp tile 64x64. SMEM row stride 20 floats (conflict-free).
#define PBM 128
#define PBN 256
#define PBK 16
#define PSTR 20
#define PSTAGES 3
#define PASTG (PBM*PSTR)
#define PBSTG (PBN*PSTR)
#define PSMEM_BYTES (PSTAGES*(PASTG+PBSTG)*4)   // 92160

__global__ __launch_bounds__(256, 1) void mma_tf32_pipe_kernel(
    const float* __restrict__ A, const float* __restrict__ B,
    float* __restrict__ C, int M, int N, int K)
{
    extern __shared__ float smem[];
    float* As = smem;                       // [PSTAGES][PASTG]
    float* Bs = smem + PSTAGES * PASTG;     // [PSTAGES][PBSTG]

    int tid = threadIdx.x, lane = tid & 31, wid = tid >> 5;
    int wm = wid & 1, wn = wid >> 1;
    int m0 = wm * 64, n0 = wn * 64;
    int lr = lane >> 2, lc = lane & 3;

    int bm = blockIdx.x * PBM;
    int bn = blockIdx.y * PBN;

    int arow0 = tid >> 2, akc = tid & 3;
    const float* Ag0 = A + (size_t)(bm + arow0) * K + akc * 4;
    const float* Ag1 = A + (size_t)(bm + arow0 + 64) * K + akc * 4;
    uint32_t sA0 = (uint32_t)__cvta_generic_to_shared(As + arow0 * PSTR + akc * 4);
    uint32_t sA1 = (uint32_t)__cvta_generic_to_shared(As + (arow0 + 64) * PSTR + akc * 4);
    const float* Bg0 = B + (size_t)(bn + arow0) * K + akc * 4;
    const float* Bg1 = B + (size_t)(bn + arow0 + 64) * K + akc * 4;
    const float* Bg2 = B + (size_t)(bn + arow0 + 128) * K + akc * 4;
    const float* Bg3 = B + (size_t)(bn + arow0 + 192) * K + akc * 4;
    uint32_t sB0 = (uint32_t)__cvta_generic_to_shared(Bs + arow0 * PSTR + akc * 4);

    float acc[4][8][4];
    #pragma unroll
    for (int mf = 0; mf < 4; mf++)
        #pragma unroll
        for (int nf = 0; nf < 8; nf++)
            #pragma unroll
            for (int r = 0; r < 4; r++) acc[mf][nf][r] = 0.f;

    const int NIT = K / PBK;   // 64

    auto load_stage = [&](int s, int kt) {
        uint32_t aoff = s * PASTG * 4;
        uint32_t boff = s * PBSTG * 4;
        int g = kt * PBK;
        cpasync16(sA0 + aoff, Ag0 + g);
        cpasync16(sA1 + aoff, Ag1 + g);
        cpasync16(sB0 + boff,                  Bg0 + g);
        cpasync16(sB0 + boff + 64*PSTR*4,      Bg1 + g);
        cpasync16(sB0 + boff + 128*PSTR*4,     Bg2 + g);
        cpasync16(sB0 + boff + 192*PSTR*4,     Bg3 + g);
    };

    load_stage(0, 0);
    asm volatile("cp.async.commit_group;");
    load_stage(1, 1);
    asm volatile("cp.async.commit_group;");

    int s = 0;
    for (int kt = 0; kt < NIT; kt++) {
        asm volatile("cp.async.wait_group 1;");
        __syncthreads();
        if (kt + 2 < NIT) load_stage((kt + 2) % PSTAGES, kt + 2);
        asm volatile("cp.async.commit_group;");

        const float* Asp = As + s * PASTG;
        const float* Bsp = Bs + s * PBSTG;
        #pragma unroll
        for (int ks = 0; ks < 2; ks++) {
            int k0 = ks * 8;
            uint32_t af[4][4], bf[8][2];
            #pragma unroll
            for (int mf = 0; mf < 4; mf++) {
                int row = m0 + mf * 16 + lr;
                af[mf][0] = __float_as_uint(Asp[row * PSTR + k0 + lc]);
                af[mf][1] = __float_as_uint(Asp[(row + 8) * PSTR + k0 + lc]);
                af[mf][2] = __float_as_uint(Asp[row * PSTR + k0 + 4 + lc]);
                af[mf][3] = __float_as_uint(Asp[(row + 8) * PSTR + k0 + 4 + lc]);
            }
            #pragma unroll
            for (int nf = 0; nf < 8; nf++) {
                int col = n0 + nf * 8 + lr;
                bf[nf][0] = __float_as_uint(Bsp[col * PSTR + k0 + lc]);
                bf[nf][1] = __float_as_uint(Bsp[col * PSTR + k0 + 4 + lc]);
            }
            #pragma unroll
            for (int mf = 0; mf < 4; mf++)
                #pragma unroll
                for (int nf = 0; nf < 8; nf++)
                    mma_tf32(acc[mf][nf], af[mf], bf[nf]);
        }
        s++; if (s == PSTAGES) s = 0;
    }

    #pragma unroll
    for (int mf = 0; mf < 4; mf++) {
        int row = bm + m0 + mf * 16 + lr;
        #pragma unroll
        for (int nf = 0; nf < 8; nf++) {
            int col = bn + n0 + nf * 8 + lc * 2;
            float2 v0 = make_float2(acc[mf][nf][0], acc[mf][nf][1]);
            float2 v1 = make_float2(acc[mf][nf][2], acc[mf][nf][3]);
            *reinterpret_cast<float2*>(&C[(size_t)row * N + col]) = v0;
            *reinterpret_cast<float2*>(&C[(size_t)(row + 8) * N + col]) = v1;
        }
    }
}

// ---------------- Grid barrier (persistent kernel, 128 co-resident blocks) ----------------
__device__ __forceinline__ void grid_barrier() {
    __threadfence();
    __syncthreads();
    if (threadIdx.x == 0) {
        unsigned int ticket = atomicAdd(&g_barrier_count, 1);
        unsigned int target = ticket - (ticket % gridDim.x) + gridDim.x;
        volatile unsigned int* p = &g_barrier_count;
        while ((int)(*p - target) < 0) { }
    }
    __syncthreads();
}

__device__ __forceinline__ float sigmoidf_(float x) { return 1.f / (1.f + expf(-x)); }

// ---------------- LSTM layer (persistent; Wh register-resident; FFMA2 inner loop) -------
// 128 blocks x 512 threads. Block owns 32 gate rows (4 chunks x 8 d's).
// h layout is [k][b] (8 floats per k): warp-broadcast LDS.128 yields 2 batch-pairs per
// load, feeding packed fma.rn.f32x2 (2 FMA/issue). g_hbuf also stored [k][b].
#define LSTM_BLOCKS 128
#define LSTM_THREADS 512

__global__ __launch_bounds__(LSTM_THREADS, 1) void lstm_layer_kernel(
    const float* __restrict__ Gx, const float* __restrict__ Wh,
    float* __restrict__ H, float* __restrict__ hn, float* __restrict__ cn)
{
    __shared__ __align__(16) float sh[DM * BB];   // h_prev [k][b], 32KB
    __shared__ float  sred[16 * 288];             // partials: stride-9 pad
    __shared__ float  sgate[256];                 // gates: [r][b]

    int tid  = threadIdx.x;
    int w    = tid >> 5;                   // warp id = k-slice 0..15 (k in [w*64,+64))
    int lane = tid & 31;                   // lane = row 0..31
    int chunk = lane >> 3, dl = lane & 7;
    int d    = blockIdx.x * 8 + dl;
    int grow = chunk * DM + d;

    float4 wreg[16];                       // this thread's 64 Wh values
    {
        const float4* wrow = reinterpret_cast<const float4*>(Wh + (size_t)grow * DM) + w * 16;
        #pragma unroll
        for (int i = 0; i < 16; i++) wreg[i] = wrow[i];
    }

    int rr = tid >> 3, bb = tid & 7;
    int grow_red = (rr >> 3) * DM + blockIdx.x * 8 + (rr & 7);

    float c_state = 0.f;
    int a_dl = tid >> 3, a_b = tid & 7;
    int a_d  = blockIdx.x * 8 + a_dl;

    for (int t = 0; t < SS; t++) {
        if (t > 0) {
            // stage h_prev ([k][b] layout) -> SMEM, bypass L1 (written by other SMs)
            const float4* hb4 = reinterpret_cast<const float4*>(g_hbuf + ((t-1)&1) * (BB*DM));
            #pragma unroll
            for (int i = tid; i < BB * 256; i += LSTM_THREADS)
                reinterpret_cast<float4*>(sh)[i] = __ldcg(hb4 + i);
        }
        __syncthreads();

        float gx = 0.f;
        if (tid < 256)
            gx = __ldg(Gx + (size_t)(bb * SS + t) * G4D + grow_red);

        unsigned long long acc2[4] = {0ull, 0ull, 0ull, 0ull};   // {b0,b1}..{b6,b7}
        if (t > 0) {
            const ulonglong2* shp =
                reinterpret_cast<const ulonglong2*>(sh + (size_t)(w * 64) * BB);
            #pragma unroll
            for (int kk = 0; kk < 64; kk++) {
                ulonglong2 h03 = shp[kk * 2];       // broadcast across warp lanes
                ulonglong2 h47 = shp[kk * 2 + 1];
                const float4& wq = wreg[kk >> 2];
                float ws = (kk & 2) ? ((kk & 1) ? wq.w : wq.z)
                                    : ((kk & 1) ? wq.y : wq.x);
                unsigned long long wp = pack2(ws);
                ffma2(acc2[0], wp, h03.x);
                ffma2(acc2[1], wp, h03.y);
                ffma2(acc2[2], wp, h47.x);
                ffma2(acc2[3], wp, h47.y);
            }
        }

        // write partials (stride-9 pad -> conflict-free)
        float* pr = &sred[(w * 32 + lane) * 9];
        #pragma unroll
        for (int j = 0; j < 4; j++) unpack2(acc2[j], pr[j*2], pr[j*2+1]);
        __syncthreads();

        if (tid < 256) {
            float sgx = gx;
            #pragma unroll
            for (int ww = 0; ww < 16; ww++)
                sgx += sred[ww * 288 + rr * 9 + bb];
            sgate[rr * 8 + bb] = sgx;
        }
        __syncthreads();

        if (tid < 64) {
            float gi = sgate[(0  + a_dl) * 8 + a_b];
            float gf = sgate[(8  + a_dl) * 8 + a_b];
            float go = sgate[(16 + a_dl) * 8 + a_b];
            float gg = sgate[(24 + a_dl) * 8 + a_b];
            float i_s = sigmoidf_(gi);
            float f_s = sigmoidf_(gf);
            float o_s = sigmoidf_(go);
            c_state = f_s * c_state + i_s * tanhf(gg);
            float h_new = o_s * tanhf(c_state);
            H[((size_t)(a_b * SS + t)) * DM + a_d] = h_new;
            g_hbuf[(t & 1) * (BB * DM) + a_d * BB + a_b] = h_new;   // [k][b] layout
            if (t == SS - 1) {
                hn[a_b * DM + a_d] = h_new;
                cn[a_b * DM + a_d] = c_state;
            }
        }
        grid_barrier();
    }
}

// ---------------- RMSNorm (one block per row; emits tf32-rounded values) ----------------
__global__ __launch_bounds__(256) void rmsnorm_kernel(const float* __restrict__ in,
                                                      const float* __restrict__ w) {
    int row = blockIdx.x;
    int tid = threadIdx.x;
    const float4* r4 = reinterpret_cast<const float4*>(in + (size_t)row * DM);
    float4 v = r4[tid];
    float s = v.x*v.x + v.y*v.y + v.z*v.z + v.w*v.w;
    #pragma unroll
    for (int o = 16; o; o >>= 1) s += __shfl_xor_sync(0xFFFFFFFFu, s, o);
    __shared__ float red[8];
    if ((tid & 31) == 0) red[tid >> 5] = s;
    __syncthreads();
    float tot = red[0]+red[1]+red[2]+red[3]+red[4]+red[5]+red[6]+red[7];
    float scale = rsqrtf(tot * (1.f/ (float)DM) + 1e-5f);
    float4 wv = reinterpret_cast<const float4*>(w)[tid];
    float4 o4;
    o4.x = __uint_as_float(f2tf32(v.x * scale * wv.x));
    o4.y = __uint_as_float(f2tf32(v.y * scale * wv.y));
    o4.z = __uint_as_float(f2tf32(v.z * scale * wv.z));
    o4.w = __uint_as_float(f2tf32(v.w * scale * wv.w));
    reinterpret_cast<float4*>(g_norm + (size_t)row * DM)[tid] = o4;
}

// ---------------- Launch ----------------
extern "C" void kernel_launch(void* const* d_in, const int* in_sizes, int n_in,
                              void* d_out, int out_size) {
    const int*   ids = (const int*)d_in[0];
    const float* emb = (const float*)d_in[1];
    const float* Wx  = (const float*)d_in[2];
    const float* bx  = (const float*)d_in[3];
    const float* Wh  = (const float*)d_in[4];
    const float* bh  = (const float*)d_in[5];
    const float* nw  = (const float*)d_in[6];
    const float* ow  = (const float*)d_in[7];

    float* out = (float*)d_out;
    float* logits = out;
    float* hn = out + (size_t)M_ROWS * VOCAB;
    float* cn = hn + (size_t)NL * BB * DM;

    float *px, *pgx, *pH0, *pH1, *pnorm, *powt;
    cudaGetSymbolAddress((void**)&px,    g_x);
    cudaGetSymbolAddress((void**)&pgx,   g_gx);
    cudaGetSymbolAddress((void**)&pH0,   g_H0);
    cudaGetSymbolAddress((void**)&pH1,   g_H1);
    cudaGetSymbolAddress((void**)&pnorm, g_norm);
    cudaGetSymbolAddress((void**)&powt,  g_owt);

    static bool attr_done = false;
    if (!attr_done) {
        cudaFuncSetAttribute(mma_tf32_pipe_kernel,
                             cudaFuncAttributeMaxDynamicSharedMemorySize, PSMEM_BYTES);
        attr_done = true;
    }

    // 0. pre-round out_weight to tf32 (independent of everything else)
    round_tf32_kernel<<<(VOCAB/4) * (DM/256), 256>>>(ow, powt);

    // 1. embeddings
    embed_kernel<<<M_ROWS * (DM/4) / 256, 256>>>(ids, emb);

    // 2. layer 0 x-gates (fp32 FFMA2)
    sgemm_nt_kernel<<<dim3(G4D/128, M_ROWS/128), 256>>>(
        px, Wx, bx, bh, pgx, M_ROWS, G4D, DM);

    // 3. layer 0 recurrence
    lstm_layer_kernel<<<LSTM_BLOCKS, LSTM_THREADS>>>(pgx, Wh, pH0, hn, cn);

    // 4. layer 1 x-gates (fp32 FFMA2)
    sgemm_nt_kernel<<<dim3(G4D/128, M_ROWS/128), 256>>>(
        pH0, Wx + (size_t)G4D*DM, bx + G4D, bh + G4D, pgx, M_ROWS, G4D, DM);

    // 5. layer 1 recurrence
    lstm_layer_kernel<<<LSTM_BLOCKS, LSTM_THREADS>>>(pgx, Wh + (size_t)G4D*DM, pH1,
                                                     hn + BB*DM, cn + BB*DM);

    // 6. RMSNorm (tf32-rounded output)
    rmsnorm_kernel<<<M_ROWS, 256>>>(pH1, nw);

    // 7. logits (pipelined tf32 mma.sync)
    mma_tf32_pipe_kernel<<<dim3(M_ROWS/PBM, VOCAB/PBN), 256, PSMEM_BYTES>>>(
        pnorm, powt, logits, M_ROWS, VOCAB, DM);
}

// round 14
// speedup vs baseline: 4.8446x; 1.1590x over previous
#include <cuda_runtime.h>
#include <cuda_bf16.h>
#include <math.h>
#include <stdint.h>

// ---------------- Problem constants ----------------
#define VOCAB 32000
#define DM    1024
#define NL    2
#define BB    8
#define SS    256
#define M_ROWS (BB*SS)          // 2048
#define G4D   (4*DM)            // 4096

// ---------------- Scratch (static device globals; no allocation) ----------------
__device__ float g_x[M_ROWS * DM];        // embeddings (tf32-rounded; feeds gate GEMM only)
__device__ float g_gx[M_ROWS * G4D];      // precomputed x-gates for current layer
__device__ float g_H0[M_ROWS * DM];       // layer-0 hidden outputs (tf32-rounded)
__device__ float g_H1[M_ROWS * DM];       // layer-1 hidden outputs (exact fp32)
__device__ float g_norm[M_ROWS * DM];     // rmsnormed (tf32-rounded values)
__device__ float g_owt[(size_t)VOCAB * DM];   // out_weight, tf32-rounded copy
__device__ float g_wxt[(size_t)NL * G4D * DM]; // Wx, tf32-rounded copy
__device__ float g_hbuf[2 * BB * DM];     // double-buffered h state, layout [k][b] (exact)
__device__ unsigned int g_barrier_count;  // grid barrier ticket counter (wrap-safe)

// ---------------- tf32 helpers ----------------
__device__ __forceinline__ uint32_t f2tf32(float x) {
    uint32_t r;
    asm("cvt.rna.tf32.f32 %0, %1;" : "=r"(r) : "f"(x));
    return r;   // f32 bit layout, low 13 mantissa bits zeroed
}
__device__ __forceinline__ void mma_tf32(float* d, const uint32_t* a, const uint32_t* b) {
    asm volatile(
        "mma.sync.aligned.m16n8k8.row.col.f32.tf32.tf32.f32 "
        "{%0,%1,%2,%3}, {%4,%5,%6,%7}, {%8,%9}, {%0,%1,%2,%3};"
        : "+f"(d[0]), "+f"(d[1]), "+f"(d[2]), "+f"(d[3])
        : "r"(a[0]), "r"(a[1]), "r"(a[2]), "r"(a[3]), "r"(b[0]), "r"(b[1]));
}
__device__ __forceinline__ void cpasync16(uint32_t saddr, const void* g) {
    asm volatile("cp.async.cg.shared.global [%0], [%1], 16;" :: "r"(saddr), "l"(g));
}

// ---------------- Embedding gather (tf32-rounded output) ----------------
__global__ __launch_bounds__(256) void embed_kernel(const int* __restrict__ ids,
                                                    const float* __restrict__ emb) {
    int idx = blockIdx.x * blockDim.x + threadIdx.x;
    int token = idx >> 8;                              // DM/4 = 256
    int d4 = idx & 255;
    int id = ids[token];
    float4 v = reinterpret_cast<const float4*>(emb + (size_t)id * DM)[d4];
    float4 o;
    o.x = __uint_as_float(f2tf32(v.x));
    o.y = __uint_as_float(f2tf32(v.y));
    o.z = __uint_as_float(f2tf32(v.z));
    o.w = __uint_as_float(f2tf32(v.w));
    reinterpret_cast<float4*>(g_x)[idx] = o;
}

// ---------------- Pre-round array to tf32 format ----------------
__global__ __launch_bounds__(256) void round_tf32_kernel(const float* __restrict__ in,
                                                         float* __restrict__ out) {
    size_t idx = (size_t)blockIdx.x * blockDim.x + threadIdx.x;   // over float4 elems
    float4 v = reinterpret_cast<const float4*>(in)[idx];
    float4 o;
    o.x = __uint_as_float(f2tf32(v.x));
    o.y = __uint_as_float(f2tf32(v.y));
    o.z = __uint_as_float(f2tf32(v.z));
    o.w = __uint_as_float(f2tf32(v.w));
    reinterpret_cast<float4*>(out)[idx] = o;
}

// ---------------- Pipelined TF32 GEMM: C[M,N] = A[M,K]*B[N,K]^T (+bias1+bias2) ----------
// Operands pre-rounded to tf32 (f32 layout). Block 128x256, BK=16, 3-stage cp.async,
// 8 warps (2m x 4n), warp tile 64x64. SMEM row stride 20 floats (conflict-free).
#define PBM 128
#define PBN 256
#define PBK 16
#define PSTR 20
#define PSTAGES 3
#define PASTG (PBM*PSTR)
#define PBSTG (PBN*PSTR)
#define PSMEM_BYTES (PSTAGES*(PASTG+PBSTG)*4)   // 92160

__global__ __launch_bounds__(256, 1) void mma_tf32_pipe_kernel(
    const float* __restrict__ A, const float* __restrict__ B,
    const float* __restrict__ bias1, const float* __restrict__ bias2,
    float* __restrict__ C, int M, int N, int K)
{
    extern __shared__ float smem[];
    float* As = smem;                       // [PSTAGES][PASTG]
    float* Bs = smem + PSTAGES * PASTG;     // [PSTAGES][PBSTG]

    int tid = threadIdx.x, lane = tid & 31, wid = tid >> 5;
    int wm = wid & 1, wn = wid >> 1;
    int m0 = wm * 64, n0 = wn * 64;
    int lr = lane >> 2, lc = lane & 3;

    int bm = blockIdx.x * PBM;
    int bn = blockIdx.y * PBN;

    int arow0 = tid >> 2, akc = tid & 3;
    const float* Ag0 = A + (size_t)(bm + arow0) * K + akc * 4;
    const float* Ag1 = A + (size_t)(bm + arow0 + 64) * K + akc * 4;
    uint32_t sA0 = (uint32_t)__cvta_generic_to_shared(As + arow0 * PSTR + akc * 4);
    uint32_t sA1 = (uint32_t)__cvta_generic_to_shared(As + (arow0 + 64) * PSTR + akc * 4);
    const float* Bg0 = B + (size_t)(bn + arow0) * K + akc * 4;
    const float* Bg1 = B + (size_t)(bn + arow0 + 64) * K + akc * 4;
    const float* Bg2 = B + (size_t)(bn + arow0 + 128) * K + akc * 4;
    const float* Bg3 = B + (size_t)(bn + arow0 + 192) * K + akc * 4;
    uint32_t sB0 = (uint32_t)__cvta_generic_to_shared(Bs + arow0 * PSTR + akc * 4);

    float acc[4][8][4];
    #pragma unroll
    for (int mf = 0; mf < 4; mf++)
        #pragma unroll
        for (int nf = 0; nf < 8; nf++)
            #pragma unroll
            for (int r = 0; r < 4; r++) acc[mf][nf][r] = 0.f;

    const int NIT = K / PBK;

    auto load_stage = [&](int s, int kt) {
        uint32_t aoff = s * PASTG * 4;
        uint32_t boff = s * PBSTG * 4;
        int g = kt * PBK;
        cpasync16(sA0 + aoff, Ag0 + g);
        cpasync16(sA1 + aoff, Ag1 + g);
        cpasync16(sB0 + boff,                  Bg0 + g);
        cpasync16(sB0 + boff + 64*PSTR*4,      Bg1 + g);
        cpasync16(sB0 + boff + 128*PSTR*4,     Bg2 + g);
        cpasync16(sB0 + boff + 192*PSTR*4,     Bg3 + g);
    };

    load_stage(0, 0);
    asm volatile("cp.async.commit_group;");
    load_stage(1, 1);
    asm volatile("cp.async.commit_group;");

    int s = 0;
    for (int kt = 0; kt < NIT; kt++) {
        asm volatile("cp.async.wait_group 1;");
        __syncthreads();
        if (kt + 2 < NIT) load_stage((kt + 2) % PSTAGES, kt + 2);
        asm volatile("cp.async.commit_group;");

        const float* Asp = As + s * PASTG;
        const float* Bsp = Bs + s * PBSTG;
        #pragma unroll
        for (int ks = 0; ks < 2; ks++) {
            int k0 = ks * 8;
            uint32_t af[4][4], bf[8][2];
            #pragma unroll
            for (int mf = 0; mf < 4; mf++) {
                int row = m0 + mf * 16 + lr;
                af[mf][0] = __float_as_uint(Asp[row * PSTR + k0 + lc]);
                af[mf][1] = __float_as_uint(Asp[(row + 8) * PSTR + k0 + lc]);
                af[mf][2] = __float_as_uint(Asp[row * PSTR + k0 + 4 + lc]);
                af[mf][3] = __float_as_uint(Asp[(row + 8) * PSTR + k0 + 4 + lc]);
            }
            #pragma unroll
            for (int nf = 0; nf < 8; nf++) {
                int col = n0 + nf * 8 + lr;
                bf[nf][0] = __float_as_uint(Bsp[col * PSTR + k0 + lc]);
                bf[nf][1] = __float_as_uint(Bsp[col * PSTR + k0 + 4 + lc]);
            }
            #pragma unroll
            for (int mf = 0; mf < 4; mf++)
                #pragma unroll
                for (int nf = 0; nf < 8; nf++)
                    mma_tf32(acc[mf][nf], af[mf], bf[nf]);
        }
        s++; if (s == PSTAGES) s = 0;
    }

    #pragma unroll
    for (int mf = 0; mf < 4; mf++) {
        int row = bm + m0 + mf * 16 + lr;
        #pragma unroll
        for (int nf = 0; nf < 8; nf++) {
            int col = bn + n0 + nf * 8 + lc * 2;
            float bs0 = 0.f, bs1 = 0.f;
            if (bias1) { bs0 += bias1[col]; bs1 += bias1[col + 1]; }
            if (bias2) { bs0 += bias2[col]; bs1 += bias2[col + 1]; }
            float2 v0 = make_float2(acc[mf][nf][0] + bs0, acc[mf][nf][1] + bs1);
            float2 v1 = make_float2(acc[mf][nf][2] + bs0, acc[mf][nf][3] + bs1);
            *reinterpret_cast<float2*>(&C[(size_t)row * N + col]) = v0;
            *reinterpret_cast<float2*>(&C[(size_t)(row + 8) * N + col]) = v1;
        }
    }
}

// ---------------- Grid barrier (persistent kernel, 128 co-resident blocks) ----------------
__device__ __forceinline__ void grid_barrier() {
    __threadfence();
    __syncthreads();
    if (threadIdx.x == 0) {
        unsigned int ticket = atomicAdd(&g_barrier_count, 1);
        unsigned int target = ticket - (ticket % gridDim.x) + gridDim.x;
        volatile unsigned int* p = &g_barrier_count;
        while ((int)(*p - target) < 0) { }
    }
    __syncthreads();
}

__device__ __forceinline__ float sigmoidf_(float x) { return 1.f / (1.f + expf(-x)); }

// ---------------- LSTM layer (persistent; Wh register-resident) ----------------
// 128 blocks x 512 threads. Block owns 32 gate rows (4 chunks x 8 d's).
// h layout [k][b]; recurrence fully fp32. round_out!=0 -> H written tf32-rounded
// (layer 0: H only feeds the next gate GEMM's A operand).
#define LSTM_BLOCKS 128
#define LSTM_THREADS 512

__global__ __launch_bounds__(LSTM_THREADS, 1) void lstm_layer_kernel(
    const float* __restrict__ Gx, const float* __restrict__ Wh,
    float* __restrict__ H, float* __restrict__ hn, float* __restrict__ cn,
    int round_out)
{
    __shared__ __align__(16) float sh[DM * BB];   // h_prev [k][b], 32KB
    __shared__ float  sred[16 * 288];             // partials: stride-9 pad
    __shared__ float  sgate[256];                 // gates: [r][b]

    int tid  = threadIdx.x;
    int w    = tid >> 5;                   // warp id = k-slice 0..15
    int lane = tid & 31;                   // lane = row 0..31
    int chunk = lane >> 3, dl = lane & 7;
    int d    = blockIdx.x * 8 + dl;
    int grow = chunk * DM + d;

    float4 wreg[16];
    {
        const float4* wrow = reinterpret_cast<const float4*>(Wh + (size_t)grow * DM) + w * 16;
        #pragma unroll
        for (int i = 0; i < 16; i++) wreg[i] = wrow[i];
    }

    int rr = tid >> 3, bb = tid & 7;
    int grow_red = (rr >> 3) * DM + blockIdx.x * 8 + (rr & 7);

    float c_state = 0.f;
    int a_dl = tid >> 3, a_b = tid & 7;
    int a_d  = blockIdx.x * 8 + a_dl;

    for (int t = 0; t < SS; t++) {
        if (t > 0) {
            const float4* hb4 = reinterpret_cast<const float4*>(g_hbuf + ((t-1)&1) * (BB*DM));
            #pragma unroll
            for (int i = tid; i < BB * 256; i += LSTM_THREADS)
                reinterpret_cast<float4*>(sh)[i] = __ldcg(hb4 + i);
        }
        __syncthreads();

        float gx = 0.f;
        if (tid < 256)
            gx = __ldg(Gx + (size_t)(bb * SS + t) * G4D + grow_red);

        float acc[8];
        #pragma unroll
        for (int b = 0; b < 8; b++) acc[b] = 0.f;
        if (t > 0) {
            const float4* shp = reinterpret_cast<const float4*>(sh + (size_t)(w * 64) * BB);
            #pragma unroll
            for (int kk = 0; kk < 64; kk++) {
                float4 h03 = shp[kk * 2];       // broadcast across warp lanes
                float4 h47 = shp[kk * 2 + 1];
                const float4& wq = wreg[kk >> 2];
                float ws = (kk & 2) ? ((kk & 1) ? wq.w : wq.z)
                                    : ((kk & 1) ? wq.y : wq.x);
                acc[0] = fmaf(ws, h03.x, acc[0]);
                acc[1] = fmaf(ws, h03.y, acc[1]);
                acc[2] = fmaf(ws, h03.z, acc[2]);
                acc[3] = fmaf(ws, h03.w, acc[3]);
                acc[4] = fmaf(ws, h47.x, acc[4]);
                acc[5] = fmaf(ws, h47.y, acc[5]);
                acc[6] = fmaf(ws, h47.z, acc[6]);
                acc[7] = fmaf(ws, h47.w, acc[7]);
            }
        }

        float* pr = &sred[(w * 32 + lane) * 9];
        #pragma unroll
        for (int b = 0; b < 8; b++) pr[b] = acc[b];
        __syncthreads();

        if (tid < 256) {
            float sgx = gx;
            #pragma unroll
            for (int ww = 0; ww < 16; ww++)
                sgx += sred[ww * 288 + rr * 9 + bb];
            sgate[rr * 8 + bb] = sgx;
        }
        __syncthreads();

        if (tid < 64) {
            float gi = sgate[(0  + a_dl) * 8 + a_b];
            float gf = sgate[(8  + a_dl) * 8 + a_b];
            float go = sgate[(16 + a_dl) * 8 + a_b];
            float gg = sgate[(24 + a_dl) * 8 + a_b];
            float i_s = sigmoidf_(gi);
            float f_s = sigmoidf_(gf);
            float o_s = sigmoidf_(go);
            c_state = f_s * c_state + i_s * tanhf(gg);
            float h_new = o_s * tanhf(c_state);
            float h_store = round_out ? __uint_as_float(f2tf32(h_new)) : h_new;
            H[((size_t)(a_b * SS + t)) * DM + a_d] = h_store;
            g_hbuf[(t & 1) * (BB * DM) + a_d * BB + a_b] = h_new;   // exact, [k][b]
            if (t == SS - 1) {
                hn[a_b * DM + a_d] = h_new;
                cn[a_b * DM + a_d] = c_state;
            }
        }
        grid_barrier();
    }
}

// ---------------- RMSNorm (one block per row; emits tf32-rounded values) ----------------
__global__ __launch_bounds__(256) void rmsnorm_kernel(const float* __restrict__ in,
                                                      const float* __restrict__ w) {
    int row = blockIdx.x;
    int tid = threadIdx.x;
    const float4* r4 = reinterpret_cast<const float4*>(in + (size_t)row * DM);
    float4 v = r4[tid];
    float s = v.x*v.x + v.y*v.y + v.z*v.z + v.w*v.w;
    #pragma unroll
    for (int o = 16; o; o >>= 1) s += __shfl_xor_sync(0xFFFFFFFFu, s, o);
    __shared__ float red[8];
    if ((tid & 31) == 0) red[tid >> 5] = s;
    __syncthreads();
    float tot = red[0]+red[1]+red[2]+red[3]+red[4]+red[5]+red[6]+red[7];
    float scale = rsqrtf(tot * (1.f/ (float)DM) + 1e-5f);
    float4 wv = reinterpret_cast<const float4*>(w)[tid];
    float4 o4;
    o4.x = __uint_as_float(f2tf32(v.x * scale * wv.x));
    o4.y = __uint_as_float(f2tf32(v.y * scale * wv.y));
    o4.z = __uint_as_float(f2tf32(v.z * scale * wv.z));
    o4.w = __uint_as_float(f2tf32(v.w * scale * wv.w));
    reinterpret_cast<float4*>(g_norm + (size_t)row * DM)[tid] = o4;
}

// ---------------- Launch ----------------
extern "C" void kernel_launch(void* const* d_in, const int* in_sizes, int n_in,
                              void* d_out, int out_size) {
    const int*   ids = (const int*)d_in[0];
    const float* emb = (const float*)d_in[1];
    const float* Wx  = (const float*)d_in[2];
    const float* bx  = (const float*)d_in[3];
    const float* Wh  = (const float*)d_in[4];
    const float* bh  = (const float*)d_in[5];
    const float* nw  = (const float*)d_in[6];
    const float* ow  = (const float*)d_in[7];

    float* out = (float*)d_out;
    float* logits = out;
    float* hn = out + (size_t)M_ROWS * VOCAB;
    float* cn = hn + (size_t)NL * BB * DM;

    float *px, *pgx, *pH0, *pH1, *pnorm, *powt, *pwxt;
    cudaGetSymbolAddress((void**)&px,    g_x);
    cudaGetSymbolAddress((void**)&pgx,   g_gx);
    cudaGetSymbolAddress((void**)&pH0,   g_H0);
    cudaGetSymbolAddress((void**)&pH1,   g_H1);
    cudaGetSymbolAddress((void**)&pnorm, g_norm);
    cudaGetSymbolAddress((void**)&powt,  g_owt);
    cudaGetSymbolAddress((void**)&pwxt,  g_wxt);

    static bool attr_done = false;
    if (!attr_done) {
        cudaFuncSetAttribute(mma_tf32_pipe_kernel,
                             cudaFuncAttributeMaxDynamicSharedMemorySize, PSMEM_BYTES);
        attr_done = true;
    }

    // 0. pre-round weights to tf32 (independent of everything else)
    round_tf32_kernel<<<(VOCAB/4) * (DM/256), 256>>>(ow, powt);
    round_tf32_kernel<<<(NL * G4D * DM / 4) / 256, 256>>>(Wx, pwxt);

    // 1. embeddings (tf32-rounded; feeds gate GEMM only)
    embed_kernel<<<M_ROWS * (DM/4) / 256, 256>>>(ids, emb);

    // 2. layer 0 x-gates (tf32 tensor cores, +bx0+bh0)
    mma_tf32_pipe_kernel<<<dim3(M_ROWS/PBM, G4D/PBN), 256, PSMEM_BYTES>>>(
        px, pwxt, bx, bh, pgx, M_ROWS, G4D, DM);

    // 3. layer 0 recurrence (H0 written tf32-rounded; recurrence exact)
    lstm_layer_kernel<<<LSTM_BLOCKS, LSTM_THREADS>>>(pgx, Wh, pH0, hn, cn, 1);

    // 4. layer 1 x-gates (tf32 tensor cores, +bx1+bh1)
    mma_tf32_pipe_kernel<<<dim3(M_ROWS/PBM, G4D/PBN), 256, PSMEM_BYTES>>>(
        pH0, pwxt + (size_t)G4D*DM, bx + G4D, bh + G4D, pgx, M_ROWS, G4D, DM);

    // 5. layer 1 recurrence (H1 exact fp32)
    lstm_layer_kernel<<<LSTM_BLOCKS, LSTM_THREADS>>>(pgx, Wh + (size_t)G4D*DM, pH1,
                                                     hn + BB*DM, cn + BB*DM, 0);

    // 6. RMSNorm (tf32-rounded output)
    rmsnorm_kernel<<<M_ROWS, 256>>>(pH1, nw);

    // 7. logits (pipelined tf32 mma.sync)
    mma_tf32_pipe_kernel<<<dim3(M_ROWS/PBM, VOCAB/PBN), 256, PSMEM_BYTES>>>(
        pnorm, powt, nullptr, nullptr, logits, M_ROWS, VOCAB, DM);
}

// round 15
// speedup vs baseline: 5.0460x; 1.0416x over previous
#include <cuda_runtime.h>
#include <cuda_bf16.h>
#include <math.h>
#include <stdint.h>

// ---------------- Problem constants ----------------
#define VOCAB 32000
#define DM    1024
#define NL    2
#define BB    8
#define SS    256
#define M_ROWS (BB*SS)          // 2048
#define G4D   (4*DM)            // 4096

// ---------------- Scratch (static device globals; no allocation) ----------------
__device__ float g_x[M_ROWS * DM];        // embeddings (tf32-rounded; feeds gate GEMM only)
__device__ float g_gx[M_ROWS * G4D];      // precomputed x-gates for current layer
__device__ float g_H0[M_ROWS * DM];       // layer-0 hidden outputs (tf32-rounded)
__device__ float g_H1[M_ROWS * DM];       // layer-1 hidden outputs (exact fp32)
__device__ float g_norm[M_ROWS * DM];     // rmsnormed (tf32-rounded values)
__device__ float g_owt[(size_t)VOCAB * DM];   // out_weight, tf32-rounded copy
__device__ float g_wxt[(size_t)NL * G4D * DM]; // Wx, tf32-rounded copy
__device__ float g_hbuf[2 * BB * DM];     // double-buffered h state, layout [k][b] (exact)
__device__ unsigned int g_barrier_count;  // grid barrier ticket counter (wrap-safe)

// ---------------- tf32 helpers ----------------
__device__ __forceinline__ uint32_t f2tf32(float x) {
    uint32_t r;
    asm("cvt.rna.tf32.f32 %0, %1;" : "=r"(r) : "f"(x));
    return r;   // f32 bit layout, low 13 mantissa bits zeroed
}
__device__ __forceinline__ void mma_tf32(float* d, const uint32_t* a, const uint32_t* b) {
    asm volatile(
        "mma.sync.aligned.m16n8k8.row.col.f32.tf32.tf32.f32 "
        "{%0,%1,%2,%3}, {%4,%5,%6,%7}, {%8,%9}, {%0,%1,%2,%3};"
        : "+f"(d[0]), "+f"(d[1]), "+f"(d[2]), "+f"(d[3])
        : "r"(a[0]), "r"(a[1]), "r"(a[2]), "r"(a[3]), "r"(b[0]), "r"(b[1]));
}
__device__ __forceinline__ void cpasync16(uint32_t saddr, const void* g) {
    asm volatile("cp.async.cg.shared.global [%0], [%1], 16;" :: "r"(saddr), "l"(g));
}

// ---------------- Embedding gather (tf32-rounded output) ----------------
__global__ __launch_bounds__(256) void embed_kernel(const int* __restrict__ ids,
                                                    const float* __restrict__ emb) {
    int idx = blockIdx.x * blockDim.x + threadIdx.x;
    int token = idx >> 8;                              // DM/4 = 256
    int d4 = idx & 255;
    int id = ids[token];
    float4 v = reinterpret_cast<const float4*>(emb + (size_t)id * DM)[d4];
    float4 o;
    o.x = __uint_as_float(f2tf32(v.x));
    o.y = __uint_as_float(f2tf32(v.y));
    o.z = __uint_as_float(f2tf32(v.z));
    o.w = __uint_as_float(f2tf32(v.w));
    reinterpret_cast<float4*>(g_x)[idx] = o;
}

// ---------------- Pre-round array to tf32 format ----------------
__global__ __launch_bounds__(256) void round_tf32_kernel(const float* __restrict__ in,
                                                         float* __restrict__ out) {
    size_t idx = (size_t)blockIdx.x * blockDim.x + threadIdx.x;   // over float4 elems
    float4 v = reinterpret_cast<const float4*>(in)[idx];
    float4 o;
    o.x = __uint_as_float(f2tf32(v.x));
    o.y = __uint_as_float(f2tf32(v.y));
    o.z = __uint_as_float(f2tf32(v.z));
    o.w = __uint_as_float(f2tf32(v.w));
    reinterpret_cast<float4*>(out)[idx] = o;
}

// ---------------- Pipelined TF32 GEMM: C[M,N] = A[M,K]*B[N,K]^T (+bias1+bias2) ----------
// Operands pre-rounded to tf32 (f32 layout). Block 128x256, BK=16, 3-stage cp.async,
// 8 warps (2m x 4n), warp tile 64x64.
// Fragment loads: one LDS.128 per (thread,row/col) covering logical k = 4*lc..4*lc+3;
// split across the two MMAs (ks0 uses .x/.y, ks1 uses .z/.w). A and B use the same
// k-slot mapping, so every logical k is counted exactly once. PSTR=16 (no padding):
// lr-parity shifts the 16B granule by 16 banks -> LDS.128 is conflict-free.
#define PBM 128
#define PBN 256
#define PBK 16
#define PSTR 16
#define PSTAGES 3
#define PASTG (PBM*PSTR)
#define PBSTG (PBN*PSTR)
#define PSMEM_BYTES (PSTAGES*(PASTG+PBSTG)*4)   // 73728

__global__ __launch_bounds__(256, 1) void mma_tf32_pipe_kernel(
    const float* __restrict__ A, const float* __restrict__ B,
    const float* __restrict__ bias1, const float* __restrict__ bias2,
    float* __restrict__ C, int M, int N, int K)
{
    extern __shared__ float smem[];
    float* As = smem;                       // [PSTAGES][PASTG]
    float* Bs = smem + PSTAGES * PASTG;     // [PSTAGES][PBSTG]

    int tid = threadIdx.x, lane = tid & 31, wid = tid >> 5;
    int wm = wid & 1, wn = wid >> 1;
    int m0 = wm * 64, n0 = wn * 64;
    int lr = lane >> 2, lc = lane & 3;

    int bm = blockIdx.x * PBM;
    int bn = blockIdx.y * PBN;

    int arow0 = tid >> 2, akc = tid & 3;
    const float* Ag0 = A + (size_t)(bm + arow0) * K + akc * 4;
    const float* Ag1 = A + (size_t)(bm + arow0 + 64) * K + akc * 4;
    uint32_t sA0 = (uint32_t)__cvta_generic_to_shared(As + arow0 * PSTR + akc * 4);
    uint32_t sA1 = (uint32_t)__cvta_generic_to_shared(As + (arow0 + 64) * PSTR + akc * 4);
    const float* Bg0 = B + (size_t)(bn + arow0) * K + akc * 4;
    const float* Bg1 = B + (size_t)(bn + arow0 + 64) * K + akc * 4;
    const float* Bg2 = B + (size_t)(bn + arow0 + 128) * K + akc * 4;
    const float* Bg3 = B + (size_t)(bn + arow0 + 192) * K + akc * 4;
    uint32_t sB0 = (uint32_t)__cvta_generic_to_shared(Bs + arow0 * PSTR + akc * 4);

    float acc[4][8][4];
    #pragma unroll
    for (int mf = 0; mf < 4; mf++)
        #pragma unroll
        for (int nf = 0; nf < 8; nf++)
            #pragma unroll
            for (int r = 0; r < 4; r++) acc[mf][nf][r] = 0.f;

    const int NIT = K / PBK;

    auto load_stage = [&](int s, int kt) {
        uint32_t aoff = s * PASTG * 4;
        uint32_t boff = s * PBSTG * 4;
        int g = kt * PBK;
        cpasync16(sA0 + aoff, Ag0 + g);
        cpasync16(sA1 + aoff, Ag1 + g);
        cpasync16(sB0 + boff,                  Bg0 + g);
        cpasync16(sB0 + boff + 64*PSTR*4,      Bg1 + g);
        cpasync16(sB0 + boff + 128*PSTR*4,     Bg2 + g);
        cpasync16(sB0 + boff + 192*PSTR*4,     Bg3 + g);
    };

    load_stage(0, 0);
    asm volatile("cp.async.commit_group;");
    load_stage(1, 1);
    asm volatile("cp.async.commit_group;");

    int s = 0;
    for (int kt = 0; kt < NIT; kt++) {
        asm volatile("cp.async.wait_group 1;");
        __syncthreads();
        if (kt + 2 < NIT) load_stage((kt + 2) % PSTAGES, kt + 2);
        asm volatile("cp.async.commit_group;");

        const float* Asp = As + s * PASTG;
        const float* Bsp = Bs + s * PBSTG;

        // vector fragment loads: 16 x LDS.128 per warp-iteration
        float4 af4[4][2];   // [mf][0]=row, [1]=row+8 ; elems = logical k 4lc..4lc+3
        float4 bf4[8];      // [nf] col = n0+nf*8+lr
        #pragma unroll
        for (int mf = 0; mf < 4; mf++) {
            int row = m0 + mf * 16 + lr;
            af4[mf][0] = *reinterpret_cast<const float4*>(&Asp[row * PSTR + lc * 4]);
            af4[mf][1] = *reinterpret_cast<const float4*>(&Asp[(row + 8) * PSTR + lc * 4]);
        }
        #pragma unroll
        for (int nf = 0; nf < 8; nf++) {
            int col = n0 + nf * 8 + lr;
            bf4[nf] = *reinterpret_cast<const float4*>(&Bsp[col * PSTR + lc * 4]);
        }

        // ks0: logical k in {4j, 4j+1}, ks1: {4j+2, 4j+3}
        #pragma unroll
        for (int ks = 0; ks < 2; ks++) {
            uint32_t af[4][4], bf[8][2];
            #pragma unroll
            for (int mf = 0; mf < 4; mf++) {
                const float4& r0 = af4[mf][0];
                const float4& r1 = af4[mf][1];
                af[mf][0] = __float_as_uint(ks ? r0.z : r0.x);
                af[mf][1] = __float_as_uint(ks ? r1.z : r1.x);
                af[mf][2] = __float_as_uint(ks ? r0.w : r0.y);
                af[mf][3] = __float_as_uint(ks ? r1.w : r1.y);
            }
            #pragma unroll
            for (int nf = 0; nf < 8; nf++) {
                const float4& c0 = bf4[nf];
                bf[nf][0] = __float_as_uint(ks ? c0.z : c0.x);
                bf[nf][1] = __float_as_uint(ks ? c0.w : c0.y);
            }
            #pragma unroll
            for (int mf = 0; mf < 4; mf++)
                #pragma unroll
                for (int nf = 0; nf < 8; nf++)
                    mma_tf32(acc[mf][nf], af[mf], bf[nf]);
        }
        s++; if (s == PSTAGES) s = 0;
    }

    #pragma unroll
    for (int mf = 0; mf < 4; mf++) {
        int row = bm + m0 + mf * 16 + lr;
        #pragma unroll
        for (int nf = 0; nf < 8; nf++) {
            int col = bn + n0 + nf * 8 + lc * 2;
            float bs0 = 0.f, bs1 = 0.f;
            if (bias1) { bs0 += bias1[col]; bs1 += bias1[col + 1]; }
            if (bias2) { bs0 += bias2[col]; bs1 += bias2[col + 1]; }
            float2 v0 = make_float2(acc[mf][nf][0] + bs0, acc[mf][nf][1] + bs1);
            float2 v1 = make_float2(acc[mf][nf][2] + bs0, acc[mf][nf][3] + bs1);
            *reinterpret_cast<float2*>(&C[(size_t)row * N + col]) = v0;
            *reinterpret_cast<float2*>(&C[(size_t)(row + 8) * N + col]) = v1;
        }
    }
}

// ---------------- Grid barrier (persistent kernel, 128 co-resident blocks) ----------------
__device__ __forceinline__ void grid_barrier() {
    __threadfence();
    __syncthreads();
    if (threadIdx.x == 0) {
        unsigned int ticket = atomicAdd(&g_barrier_count, 1);
        unsigned int target = ticket - (ticket % gridDim.x) + gridDim.x;
        volatile unsigned int* p = &g_barrier_count;
        while ((int)(*p - target) < 0) { }
    }
    __syncthreads();
}

__device__ __forceinline__ float sigmoidf_(float x) { return 1.f / (1.f + expf(-x)); }

// ---------------- LSTM layer (persistent; Wh register-resident) ----------------
#define LSTM_BLOCKS 128
#define LSTM_THREADS 512

__global__ __launch_bounds__(LSTM_THREADS, 1) void lstm_layer_kernel(
    const float* __restrict__ Gx, const float* __restrict__ Wh,
    float* __restrict__ H, float* __restrict__ hn, float* __restrict__ cn,
    int round_out)
{
    __shared__ __align__(16) float sh[DM * BB];   // h_prev [k][b], 32KB
    __shared__ float  sred[16 * 288];             // partials: stride-9 pad
    __shared__ float  sgate[256];                 // gates: [r][b]

    int tid  = threadIdx.x;
    int w    = tid >> 5;
    int lane = tid & 31;
    int chunk = lane >> 3, dl = lane & 7;
    int d    = blockIdx.x * 8 + dl;
    int grow = chunk * DM + d;

    float4 wreg[16];
    {
        const float4* wrow = reinterpret_cast<const float4*>(Wh + (size_t)grow * DM) + w * 16;
        #pragma unroll
        for (int i = 0; i < 16; i++) wreg[i] = wrow[i];
    }

    int rr = tid >> 3, bb = tid & 7;
    int grow_red = (rr >> 3) * DM + blockIdx.x * 8 + (rr & 7);

    float c_state = 0.f;
    int a_dl = tid >> 3, a_b = tid & 7;
    int a_d  = blockIdx.x * 8 + a_dl;

    for (int t = 0; t < SS; t++) {
        if (t > 0) {
            const float4* hb4 = reinterpret_cast<const float4*>(g_hbuf + ((t-1)&1) * (BB*DM));
            #pragma unroll
            for (int i = tid; i < BB * 256; i += LSTM_THREADS)
                reinterpret_cast<float4*>(sh)[i] = __ldcg(hb4 + i);
        }
        __syncthreads();

        float gx = 0.f;
        if (tid < 256)
            gx = __ldg(Gx + (size_t)(bb * SS + t) * G4D + grow_red);

        float acc[8];
        #pragma unroll
        for (int b = 0; b < 8; b++) acc[b] = 0.f;
        if (t > 0) {
            const float4* shp = reinterpret_cast<const float4*>(sh + (size_t)(w * 64) * BB);
            #pragma unroll
            for (int kk = 0; kk < 64; kk++) {
                float4 h03 = shp[kk * 2];
                float4 h47 = shp[kk * 2 + 1];
                const float4& wq = wreg[kk >> 2];
                float ws = (kk & 2) ? ((kk & 1) ? wq.w : wq.z)
                                    : ((kk & 1) ? wq.y : wq.x);
                acc[0] = fmaf(ws, h03.x, acc[0]);
                acc[1] = fmaf(ws, h03.y, acc[1]);
                acc[2] = fmaf(ws, h03.z, acc[2]);
                acc[3] = fmaf(ws, h03.w, acc[3]);
                acc[4] = fmaf(ws, h47.x, acc[4]);
                acc[5] = fmaf(ws, h47.y, acc[5]);
                acc[6] = fmaf(ws, h47.z, acc[6]);
                acc[7] = fmaf(ws, h47.w, acc[7]);
            }
        }

        float* pr = &sred[(w * 32 + lane) * 9];
        #pragma unroll
        for (int b = 0; b < 8; b++) pr[b] = acc[b];
        __syncthreads();

        if (tid < 256) {
            float sgx = gx;
            #pragma unroll
            for (int ww = 0; ww < 16; ww++)
                sgx += sred[ww * 288 + rr * 9 + bb];
            sgate[rr * 8 + bb] = sgx;
        }
        __syncthreads();

        if (tid < 64) {
            float gi = sgate[(0  + a_dl) * 8 + a_b];
            float gf = sgate[(8  + a_dl) * 8 + a_b];
            float go = sgate[(16 + a_dl) * 8 + a_b];
            float gg = sgate[(24 + a_dl) * 8 + a_b];
            float i_s = sigmoidf_(gi);
            float f_s = sigmoidf_(gf);
            float o_s = sigmoidf_(go);
            c_state = f_s * c_state + i_s * tanhf(gg);
            float h_new = o_s * tanhf(c_state);
            float h_store = round_out ? __uint_as_float(f2tf32(h_new)) : h_new;
            H[((size_t)(a_b * SS + t)) * DM + a_d] = h_store;
            g_hbuf[(t & 1) * (BB * DM) + a_d * BB + a_b] = h_new;   // exact, [k][b]
            if (t == SS - 1) {
                hn[a_b * DM + a_d] = h_new;
                cn[a_b * DM + a_d] = c_state;
            }
        }
        grid_barrier();
    }
}

// ---------------- RMSNorm (one block per row; emits tf32-rounded values) ----------------
__global__ __launch_bounds__(256) void rmsnorm_kernel(const float* __restrict__ in,
                                                      const float* __restrict__ w) {
    int row = blockIdx.x;
    int tid = threadIdx.x;
    const float4* r4 = reinterpret_cast<const float4*>(in + (size_t)row * DM);
    float4 v = r4[tid];
    float s = v.x*v.x + v.y*v.y + v.z*v.z + v.w*v.w;
    #pragma unroll
    for (int o = 16; o; o >>= 1) s += __shfl_xor_sync(0xFFFFFFFFu, s, o);
    __shared__ float red[8];
    if ((tid & 31) == 0) red[tid >> 5] = s;
    __syncthreads();
    float tot = red[0]+red[1]+red[2]+red[3]+red[4]+red[5]+red[6]+red[7];
    float scale = rsqrtf(tot * (1.f/ (float)DM) + 1e-5f);
    float4 wv = reinterpret_cast<const float4*>(w)[tid];
    float4 o4;
    o4.x = __uint_as_float(f2tf32(v.x * scale * wv.x));
    o4.y = __uint_as_float(f2tf32(v.y * scale * wv.y));
    o4.z = __uint_as_float(f2tf32(v.z * scale * wv.z));
    o4.w = __uint_as_float(f2tf32(v.w * scale * wv.w));
    reinterpret_cast<float4*>(g_norm + (size_t)row * DM)[tid] = o4;
}

// ---------------- Launch ----------------
extern "C" void kernel_launch(void* const* d_in, const int* in_sizes, int n_in,
                              void* d_out, int out_size) {
    const int*   ids = (const int*)d_in[0];
    const float* emb = (const float*)d_in[1];
    const float* Wx  = (const float*)d_in[2];
    const float* bx  = (const float*)d_in[3];
    const float* Wh  = (const float*)d_in[4];
    const float* bh  = (const float*)d_in[5];
    const float* nw  = (const float*)d_in[6];
    const float* ow  = (const float*)d_in[7];

    float* out = (float*)d_out;
    float* logits = out;
    float* hn = out + (size_t)M_ROWS * VOCAB;
    float* cn = hn + (size_t)NL * BB * DM;

    float *px, *pgx, *pH0, *pH1, *pnorm, *powt, *pwxt;
    cudaGetSymbolAddress((void**)&px,    g_x);
    cudaGetSymbolAddress((void**)&pgx,   g_gx);
    cudaGetSymbolAddress((void**)&pH0,   g_H0);
    cudaGetSymbolAddress((void**)&pH1,   g_H1);
    cudaGetSymbolAddress((void**)&pnorm, g_norm);
    cudaGetSymbolAddress((void**)&powt,  g_owt);
    cudaGetSymbolAddress((void**)&pwxt,  g_wxt);

    static bool attr_done = false;
    if (!attr_done) {
        cudaFuncSetAttribute(mma_tf32_pipe_kernel,
                             cudaFuncAttributeMaxDynamicSharedMemorySize, PSMEM_BYTES);
        attr_done = true;
    }

    // 0. pre-round weights to tf32 (independent of everything else)
    round_tf32_kernel<<<(VOCAB/4) * (DM/256), 256>>>(ow, powt);
    round_tf32_kernel<<<(NL * G4D * DM / 4) / 256, 256>>>(Wx, pwxt);

    // 1. embeddings (tf32-rounded; feeds gate GEMM only)
    embed_kernel<<<M_ROWS * (DM/4) / 256, 256>>>(ids, emb);

    // 2. layer 0 x-gates (tf32 tensor cores, +bx0+bh0)
    mma_tf32_pipe_kernel<<<dim3(M_ROWS/PBM, G4D/PBN), 256, PSMEM_BYTES>>>(
        px, pwxt, bx, bh, pgx, M_ROWS, G4D, DM);

    // 3. layer 0 recurrence (H0 written tf32-rounded; recurrence exact)
    lstm_layer_kernel<<<LSTM_BLOCKS, LSTM_THREADS>>>(pgx, Wh, pH0, hn, cn, 1);

    // 4. layer 1 x-gates (tf32 tensor cores, +bx1+bh1)
    mma_tf32_pipe_kernel<<<dim3(M_ROWS/PBM, G4D/PBN), 256, PSMEM_BYTES>>>(
        pH0, pwxt + (size_t)G4D*DM, bx + G4D, bh + G4D, pgx, M_ROWS, G4D, DM);

    // 5. layer 1 recurrence (H1 exact fp32)
    lstm_layer_kernel<<<LSTM_BLOCKS, LSTM_THREADS>>>(pgx, Wh + (size_t)G4D*DM, pH1,
                                                     hn + BB*DM, cn + BB*DM, 0);

    // 6. RMSNorm (tf32-rounded output)
    rmsnorm_kernel<<<M_ROWS, 256>>>(pH1, nw);

    // 7. logits (pipelined tf32 mma.sync)
    mma_tf32_pipe_kernel<<<dim3(M_ROWS/PBM, VOCAB/PBN), 256, PSMEM_BYTES>>>(
        pnorm, powt, nullptr, nullptr, logits, M_ROWS, VOCAB, DM);
}

// round 16
// speedup vs baseline: 6.5282x; 1.2937x over previous
#include <cuda_runtime.h>
#include <cuda_bf16.h>
#include <math.h>
#include <stdint.h>

// ---------------- Problem constants ----------------
#define VOCAB 32000
#define DM    1024
#define NL    2
#define BB    8
#define SS    256
#define M_ROWS (BB*SS)          // 2048
#define G4D   (4*DM)            // 4096

// ---------------- Scratch (static device globals; no allocation) ----------------
__device__ float g_x[M_ROWS * DM];        // embeddings (tf32-rounded; feeds gate GEMM only)
__device__ float g_gx[M_ROWS * G4D];      // precomputed x-gates for current layer
__device__ float g_H0[M_ROWS * DM];       // layer-0 hidden outputs (tf32-rounded)
__device__ float g_H1[M_ROWS * DM];       // layer-1 hidden outputs (exact fp32)
__device__ float g_norm[M_ROWS * DM];     // rmsnormed (tf32-rounded values)
__device__ float g_owt[(size_t)VOCAB * DM];   // out_weight, tf32-rounded copy
__device__ float g_wxt[(size_t)NL * G4D * DM]; // Wx, tf32-rounded copy
__device__ float g_hbuf[2 * BB * DM];     // double-buffered h state, [k][b], tf32-rounded
__device__ unsigned int g_barrier_count;  // grid barrier ticket counter (wrap-safe)

// ---------------- tf32 helpers ----------------
__device__ __forceinline__ uint32_t f2tf32(float x) {
    uint32_t r;
    asm("cvt.rna.tf32.f32 %0, %1;" : "=r"(r) : "f"(x));
    return r;   // f32 bit layout, low 13 mantissa bits zeroed
}
__device__ __forceinline__ void mma_tf32(float* d, const uint32_t* a, const uint32_t* b) {
    asm volatile(
        "mma.sync.aligned.m16n8k8.row.col.f32.tf32.tf32.f32 "
        "{%0,%1,%2,%3}, {%4,%5,%6,%7}, {%8,%9}, {%0,%1,%2,%3};"
        : "+f"(d[0]), "+f"(d[1]), "+f"(d[2]), "+f"(d[3])
        : "r"(a[0]), "r"(a[1]), "r"(a[2]), "r"(a[3]), "r"(b[0]), "r"(b[1]));
}
__device__ __forceinline__ void cpasync16(uint32_t saddr, const void* g) {
    asm volatile("cp.async.cg.shared.global [%0], [%1], 16;" :: "r"(saddr), "l"(g));
}

// ---------------- Embedding gather (tf32-rounded output) ----------------
__global__ __launch_bounds__(256) void embed_kernel(const int* __restrict__ ids,
                                                    const float* __restrict__ emb) {
    int idx = blockIdx.x * blockDim.x + threadIdx.x;
    int token = idx >> 8;                              // DM/4 = 256
    int d4 = idx & 255;
    int id = ids[token];
    float4 v = reinterpret_cast<const float4*>(emb + (size_t)id * DM)[d4];
    float4 o;
    o.x = __uint_as_float(f2tf32(v.x));
    o.y = __uint_as_float(f2tf32(v.y));
    o.z = __uint_as_float(f2tf32(v.z));
    o.w = __uint_as_float(f2tf32(v.w));
    reinterpret_cast<float4*>(g_x)[idx] = o;
}

// ---------------- Pre-round array to tf32 format ----------------
__global__ __launch_bounds__(256) void round_tf32_kernel(const float* __restrict__ in,
                                                         float* __restrict__ out) {
    size_t idx = (size_t)blockIdx.x * blockDim.x + threadIdx.x;   // over float4 elems
    float4 v = reinterpret_cast<const float4*>(in)[idx];
    float4 o;
    o.x = __uint_as_float(f2tf32(v.x));
    o.y = __uint_as_float(f2tf32(v.y));
    o.z = __uint_as_float(f2tf32(v.z));
    o.w = __uint_as_float(f2tf32(v.w));
    reinterpret_cast<float4*>(out)[idx] = o;
}

// ---------------- Pipelined TF32 GEMM: C[M,N] = A[M,K]*B[N,K]^T (+bias1+bias2) ----------
#define PBM 128
#define PBN 256
#define PBK 16
#define PSTR 16
#define PSTAGES 3
#define PASTG (PBM*PSTR)
#define PBSTG (PBN*PSTR)
#define PSMEM_BYTES (PSTAGES*(PASTG+PBSTG)*4)   // 73728

__global__ __launch_bounds__(256, 1) void mma_tf32_pipe_kernel(
    const float* __restrict__ A, const float* __restrict__ B,
    const float* __restrict__ bias1, const float* __restrict__ bias2,
    float* __restrict__ C, int M, int N, int K)
{
    extern __shared__ float smem[];
    float* As = smem;                       // [PSTAGES][PASTG]
    float* Bs = smem + PSTAGES * PASTG;     // [PSTAGES][PBSTG]

    int tid = threadIdx.x, lane = tid & 31, wid = tid >> 5;
    int wm = wid & 1, wn = wid >> 1;
    int m0 = wm * 64, n0 = wn * 64;
    int lr = lane >> 2, lc = lane & 3;

    int bm = blockIdx.x * PBM;
    int bn = blockIdx.y * PBN;

    int arow0 = tid >> 2, akc = tid & 3;
    const float* Ag0 = A + (size_t)(bm + arow0) * K + akc * 4;
    const float* Ag1 = A + (size_t)(bm + arow0 + 64) * K + akc * 4;
    uint32_t sA0 = (uint32_t)__cvta_generic_to_shared(As + arow0 * PSTR + akc * 4);
    uint32_t sA1 = (uint32_t)__cvta_generic_to_shared(As + (arow0 + 64) * PSTR + akc * 4);
    const float* Bg0 = B + (size_t)(bn + arow0) * K + akc * 4;
    const float* Bg1 = B + (size_t)(bn + arow0 + 64) * K + akc * 4;
    const float* Bg2 = B + (size_t)(bn + arow0 + 128) * K + akc * 4;
    const float* Bg3 = B + (size_t)(bn + arow0 + 192) * K + akc * 4;
    uint32_t sB0 = (uint32_t)__cvta_generic_to_shared(Bs + arow0 * PSTR + akc * 4);

    float acc[4][8][4];
    #pragma unroll
    for (int mf = 0; mf < 4; mf++)
        #pragma unroll
        for (int nf = 0; nf < 8; nf++)
            #pragma unroll
            for (int r = 0; r < 4; r++) acc[mf][nf][r] = 0.f;

    const int NIT = K / PBK;

    auto load_stage = [&](int s, int kt) {
        uint32_t aoff = s * PASTG * 4;
        uint32_t boff = s * PBSTG * 4;
        int g = kt * PBK;
        cpasync16(sA0 + aoff, Ag0 + g);
        cpasync16(sA1 + aoff, Ag1 + g);
        cpasync16(sB0 + boff,                  Bg0 + g);
        cpasync16(sB0 + boff + 64*PSTR*4,      Bg1 + g);
        cpasync16(sB0 + boff + 128*PSTR*4,     Bg2 + g);
        cpasync16(sB0 + boff + 192*PSTR*4,     Bg3 + g);
    };

    load_stage(0, 0);
    asm volatile("cp.async.commit_group;");
    load_stage(1, 1);
    asm volatile("cp.async.commit_group;");

    int s = 0;
    for (int kt = 0; kt < NIT; kt++) {
        asm volatile("cp.async.wait_group 1;");
        __syncthreads();
        if (kt + 2 < NIT) load_stage((kt + 2) % PSTAGES, kt + 2);
        asm volatile("cp.async.commit_group;");

        const float* Asp = As + s * PASTG;
        const float* Bsp = Bs + s * PBSTG;

        float4 af4[4][2];
        float4 bf4[8];
        #pragma unroll
        for (int mf = 0; mf < 4; mf++) {
            int row = m0 + mf * 16 + lr;
            af4[mf][0] = *reinterpret_cast<const float4*>(&Asp[row * PSTR + lc * 4]);
            af4[mf][1] = *reinterpret_cast<const float4*>(&Asp[(row + 8) * PSTR + lc * 4]);
        }
        #pragma unroll
        for (int nf = 0; nf < 8; nf++) {
            int col = n0 + nf * 8 + lr;
            bf4[nf] = *reinterpret_cast<const float4*>(&Bsp[col * PSTR + lc * 4]);
        }

        #pragma unroll
        for (int ks = 0; ks < 2; ks++) {
            uint32_t af[4][4], bf[8][2];
            #pragma unroll
            for (int mf = 0; mf < 4; mf++) {
                const float4& r0 = af4[mf][0];
                const float4& r1 = af4[mf][1];
                af[mf][0] = __float_as_uint(ks ? r0.z : r0.x);
                af[mf][1] = __float_as_uint(ks ? r1.z : r1.x);
                af[mf][2] = __float_as_uint(ks ? r0.w : r0.y);
                af[mf][3] = __float_as_uint(ks ? r1.w : r1.y);
            }
            #pragma unroll
            for (int nf = 0; nf < 8; nf++) {
                const float4& c0 = bf4[nf];
                bf[nf][0] = __float_as_uint(ks ? c0.z : c0.x);
                bf[nf][1] = __float_as_uint(ks ? c0.w : c0.y);
            }
            #pragma unroll
            for (int mf = 0; mf < 4; mf++)
                #pragma unroll
                for (int nf = 0; nf < 8; nf++)
                    mma_tf32(acc[mf][nf], af[mf], bf[nf]);
        }
        s++; if (s == PSTAGES) s = 0;
    }

    #pragma unroll
    for (int mf = 0; mf < 4; mf++) {
        int row = bm + m0 + mf * 16 + lr;
        #pragma unroll
        for (int nf = 0; nf < 8; nf++) {
            int col = bn + n0 + nf * 8 + lc * 2;
            float bs0 = 0.f, bs1 = 0.f;
            if (bias1) { bs0 += bias1[col]; bs1 += bias1[col + 1]; }
            if (bias2) { bs0 += bias2[col]; bs1 += bias2[col + 1]; }
            float2 v0 = make_float2(acc[mf][nf][0] + bs0, acc[mf][nf][1] + bs1);
            float2 v1 = make_float2(acc[mf][nf][2] + bs0, acc[mf][nf][3] + bs1);
            *reinterpret_cast<float2*>(&C[(size_t)row * N + col]) = v0;
            *reinterpret_cast<float2*>(&C[(size_t)(row + 8) * N + col]) = v1;
        }
    }
}

// ---------------- Grid barrier (persistent kernel, 128 co-resident blocks) ----------------
__device__ __forceinline__ void grid_barrier() {
    __threadfence();
    __syncthreads();
    if (threadIdx.x == 0) {
        unsigned int ticket = atomicAdd(&g_barrier_count, 1);
        unsigned int target = ticket - (ticket % gridDim.x) + gridDim.x;
        volatile unsigned int* p = &g_barrier_count;
        while ((int)(*p - target) < 0) { }
    }
    __syncthreads();
}

__device__ __forceinline__ float sigmoidf_(float x) { return 1.f / (1.f + expf(-x)); }

// ---------------- LSTM layer (persistent; tensor-core recurrence) ----------------
// 128 blocks x 512 threads. Block owns 32 gate rows (n_local 0..31: chunk=n>>3, dl=n&7).
// Per step: gates[n][b] = Gx + h_prev @ Wh^T computed via mma.sync m16n8k8 tf32:
//   M=16 (8 batches + 8 zero-pad), N=32 (block's gate rows), K=1024 (16 warps x 64 k).
// Wh held permanently in registers as pre-built tf32 B-fragments (64 regs/thread).
// h_prev staged [k][b] in SMEM (tf32-rounded values); A-fragment loads are
// conflict-free LDS.32. Cross-warp k-reduction via sred (same scheme as before).
#define LSTM_BLOCKS 128
#define LSTM_THREADS 512

__global__ __launch_bounds__(LSTM_THREADS, 1) void lstm_layer_kernel(
    const float* __restrict__ Gx, const float* __restrict__ Wh,
    float* __restrict__ H, float* __restrict__ hn, float* __restrict__ cn,
    int round_out)
{
    __shared__ __align__(16) float sh[DM * BB];   // h_prev [k][b], 32KB (tf32 values)
    __shared__ float  sred[16 * 288];             // partials: [w][n*9 + b], stride-9 pad
    __shared__ float  sgate[256];                 // gates: [n][b]

    int tid  = threadIdx.x;
    int w    = tid >> 5;                   // warp id = k-slice 0..15 (k in [w*64,+64))
    int lane = tid & 31;
    int lr = lane >> 2, lc = lane & 3;     // fragment row/col

    // One-time: build Wh B-fragments (tf32) in registers.
    // wfrag[kt][nf][0] = Wh[row(n=nf*8+lr)][w*64+kt*8+lc], [1] = ...+4+lc
    uint32_t wfrag[8][4][2];
    #pragma unroll
    for (int kt = 0; kt < 8; kt++)
        #pragma unroll
        for (int nf = 0; nf < 4; nf++) {
            int n = nf * 8 + lr;
            int grow = (n >> 3) * DM + blockIdx.x * 8 + (n & 7);
            const float* wr = Wh + (size_t)grow * DM + w * 64 + kt * 8;
            wfrag[kt][nf][0] = f2tf32(wr[lc]);
            wfrag[kt][nf][1] = f2tf32(wr[4 + lc]);
        }

    // Reduction mapping (tid < 256): rr = n_local, bb = batch
    int rr = tid >> 3, bb = tid & 7;
    int grow_red = (rr >> 3) * DM + blockIdx.x * 8 + (rr & 7);

    // Activation mapping (tid < 64): c lives in regs for all 256 steps
    float c_state = 0.f;
    int a_dl = tid >> 3, a_b = tid & 7;
    int a_d  = blockIdx.x * 8 + a_dl;

    for (int t = 0; t < SS; t++) {
        if (t > 0) {
            // stage h_prev ([k][b], tf32 values) -> SMEM, bypass L1
            const float4* hb4 = reinterpret_cast<const float4*>(g_hbuf + ((t-1)&1) * (BB*DM));
            #pragma unroll
            for (int i = tid; i < BB * 256; i += LSTM_THREADS)
                reinterpret_cast<float4*>(sh)[i] = __ldcg(hb4 + i);
        }
        __syncthreads();

        float gx = 0.f;
        if (tid < 256)
            gx = __ldg(Gx + (size_t)(bb * SS + t) * G4D + grow_red);

        // mma over this warp's 64-k slice: 8 k-tiles x 4 n-tiles
        float acc[4][4];
        #pragma unroll
        for (int nf = 0; nf < 4; nf++)
            #pragma unroll
            for (int r = 0; r < 4; r++) acc[nf][r] = 0.f;
        if (t > 0) {
            const float* shw = sh + (size_t)(w * 64) * BB;
            #pragma unroll
            for (int kt = 0; kt < 8; kt++) {
                // A frag: rows 0-7 = batches (b = lr), rows 8-15 = zero pad
                uint32_t af[4];
                af[0] = __float_as_uint(shw[(kt * 8 + lc) * BB + lr]);
                af[1] = 0u;
                af[2] = __float_as_uint(shw[(kt * 8 + 4 + lc) * BB + lr]);
                af[3] = 0u;
                #pragma unroll
                for (int nf = 0; nf < 4; nf++)
                    mma_tf32(acc[nf], af, wfrag[kt][nf]);
            }
        }

        // write partials: d0 -> n = nf*8 + 2*lc, d1 -> n+1, batch = lr
        #pragma unroll
        for (int nf = 0; nf < 4; nf++) {
            int n0 = nf * 8 + 2 * lc;
            sred[w * 288 + n0 * 9 + lr]       = acc[nf][0];
            sred[w * 288 + (n0 + 1) * 9 + lr] = acc[nf][1];
        }
        __syncthreads();

        // reduce over 16 k-slices, add Gx, stage gate
        if (tid < 256) {
            float sgx = gx;
            #pragma unroll
            for (int ww = 0; ww < 16; ww++)
                sgx += sred[ww * 288 + rr * 9 + bb];
            sgate[rr * 8 + bb] = sgx;
        }
        __syncthreads();

        // activation + state update
        if (tid < 64) {
            float gi = sgate[(0  + a_dl) * 8 + a_b];
            float gf = sgate[(8  + a_dl) * 8 + a_b];
            float go = sgate[(16 + a_dl) * 8 + a_b];
            float gg = sgate[(24 + a_dl) * 8 + a_b];
            float i_s = sigmoidf_(gi);
            float f_s = sigmoidf_(gf);
            float o_s = sigmoidf_(go);
            c_state = f_s * c_state + i_s * tanhf(gg);
            float h_new = o_s * tanhf(c_state);
            float h_store = round_out ? __uint_as_float(f2tf32(h_new)) : h_new;
            H[((size_t)(a_b * SS + t)) * DM + a_d] = h_store;
            // hbuf feeds only the mma A operand -> store tf32-rounded
            g_hbuf[(t & 1) * (BB * DM) + a_d * BB + a_b] = __uint_as_float(f2tf32(h_new));
            if (t == SS - 1) {
                hn[a_b * DM + a_d] = h_new;    // exact
                cn[a_b * DM + a_d] = c_state;  // exact
            }
        }
        grid_barrier();
    }
}

// ---------------- RMSNorm (one block per row; emits tf32-rounded values) ----------------
__global__ __launch_bounds__(256) void rmsnorm_kernel(const float* __restrict__ in,
                                                      const float* __restrict__ w) {
    int row = blockIdx.x;
    int tid = threadIdx.x;
    const float4* r4 = reinterpret_cast<const float4*>(in + (size_t)row * DM);
    float4 v = r4[tid];
    float s = v.x*v.x + v.y*v.y + v.z*v.z + v.w*v.w;
    #pragma unroll
    for (int o = 16; o; o >>= 1) s += __shfl_xor_sync(0xFFFFFFFFu, s, o);
    __shared__ float red[8];
    if ((tid & 31) == 0) red[tid >> 5] = s;
    __syncthreads();
    float tot = red[0]+red[1]+red[2]+red[3]+red[4]+red[5]+red[6]+red[7];
    float scale = rsqrtf(tot * (1.f/ (float)DM) + 1e-5f);
    float4 wv = reinterpret_cast<const float4*>(w)[tid];
    float4 o4;
    o4.x = __uint_as_float(f2tf32(v.x * scale * wv.x));
    o4.y = __uint_as_float(f2tf32(v.y * scale * wv.y));
    o4.z = __uint_as_float(f2tf32(v.z * scale * wv.z));
    o4.w = __uint_as_float(f2tf32(v.w * scale * wv.w));
    reinterpret_cast<float4*>(g_norm + (size_t)row * DM)[tid] = o4;
}

// ---------------- Launch ----------------
extern "C" void kernel_launch(void* const* d_in, const int* in_sizes, int n_in,
                              void* d_out, int out_size) {
    const int*   ids = (const int*)d_in[0];
    const float* emb = (const float*)d_in[1];
    const float* Wx  = (const float*)d_in[2];
    const float* bx  = (const float*)d_in[3];
    const float* Wh  = (const float*)d_in[4];
    const float* bh  = (const float*)d_in[5];
    const float* nw  = (const float*)d_in[6];
    const float* ow  = (const float*)d_in[7];

    float* out = (float*)d_out;
    float* logits = out;
    float* hn = out + (size_t)M_ROWS * VOCAB;
    float* cn = hn + (size_t)NL * BB * DM;

    float *px, *pgx, *pH0, *pH1, *pnorm, *powt, *pwxt;
    cudaGetSymbolAddress((void**)&px,    g_x);
    cudaGetSymbolAddress((void**)&pgx,   g_gx);
    cudaGetSymbolAddress((void**)&pH0,   g_H0);
    cudaGetSymbolAddress((void**)&pH1,   g_H1);
    cudaGetSymbolAddress((void**)&pnorm, g_norm);
    cudaGetSymbolAddress((void**)&powt,  g_owt);
    cudaGetSymbolAddress((void**)&pwxt,  g_wxt);

    static bool attr_done = false;
    if (!attr_done) {
        cudaFuncSetAttribute(mma_tf32_pipe_kernel,
                             cudaFuncAttributeMaxDynamicSharedMemorySize, PSMEM_BYTES);
        attr_done = true;
    }

    // 0. pre-round weights to tf32 (independent of everything else)
    round_tf32_kernel<<<(VOCAB/4) * (DM/256), 256>>>(ow, powt);
    round_tf32_kernel<<<(NL * G4D * DM / 4) / 256, 256>>>(Wx, pwxt);

    // 1. embeddings (tf32-rounded; feeds gate GEMM only)
    embed_kernel<<<M_ROWS * (DM/4) / 256, 256>>>(ids, emb);

    // 2. layer 0 x-gates (tf32 tensor cores, +bx0+bh0)
    mma_tf32_pipe_kernel<<<dim3(M_ROWS/PBM, G4D/PBN), 256, PSMEM_BYTES>>>(
        px, pwxt, bx, bh, pgx, M_ROWS, G4D, DM);

    // 3. layer 0 recurrence (tensor-core; H0 written tf32-rounded)
    lstm_layer_kernel<<<LSTM_BLOCKS, LSTM_THREADS>>>(pgx, Wh, pH0, hn, cn, 1);

    // 4. layer 1 x-gates (tf32 tensor cores, +bx1+bh1)
    mma_tf32_pipe_kernel<<<dim3(M_ROWS/PBM, G4D/PBN), 256, PSMEM_BYTES>>>(
        pH0, pwxt + (size_t)G4D*DM, bx + G4D, bh + G4D, pgx, M_ROWS, G4D, DM);

    // 5. layer 1 recurrence (tensor-core; H1 exact fp32)
    lstm_layer_kernel<<<LSTM_BLOCKS, LSTM_THREADS>>>(pgx, Wh + (size_t)G4D*DM, pH1,
                                                     hn + BB*DM, cn + BB*DM, 0);

    // 6. RMSNorm (tf32-rounded output)
    rmsnorm_kernel<<<M_ROWS, 256>>>(pH1, nw);

    // 7. logits (pipelined tf32 mma.sync)
    mma_tf32_pipe_kernel<<<dim3(M_ROWS/PBM, VOCAB/PBN), 256, PSMEM_BYTES>>>(
        pnorm, powt, nullptr, nullptr, logits, M_ROWS, VOCAB, DM);
}

// round 17
// speedup vs baseline: 6.8093x; 1.0431x over previous
#include <cuda_runtime.h>
#include <cuda_bf16.h>
#include <math.h>
#include <stdint.h>

// ---------------- Problem constants ----------------
#define VOCAB 32000
#define DM    1024
#define NL    2
#define BB    8
#define SS    256
#define M_ROWS (BB*SS)          // 2048
#define G4D   (4*DM)            // 4096

// ---------------- Scratch (static device globals; no allocation) ----------------
__device__ float g_x[M_ROWS * DM];        // embeddings (tf32-rounded; feeds gate GEMM only)
__device__ float g_gx[M_ROWS * G4D];      // precomputed x-gates for current layer
__device__ float g_H0[M_ROWS * DM];       // layer-0 hidden outputs (tf32-rounded)
__device__ float g_H1[M_ROWS * DM];       // layer-1 hidden outputs (exact fp32)
__device__ float g_norm[M_ROWS * DM];     // rmsnormed (tf32-rounded values)
__device__ float g_owt[(size_t)VOCAB * DM];   // out_weight, tf32-rounded copy
__device__ float g_wxt[(size_t)NL * G4D * DM]; // Wx, tf32-rounded copy
__device__ float g_hbuf[2 * BB * DM];     // double-buffered h state, [k][b], tf32-rounded
__device__ unsigned int g_barrier_count;  // grid barrier ticket counter (wrap-safe)

// ---------------- tf32 helpers ----------------
__device__ __forceinline__ uint32_t f2tf32(float x) {
    uint32_t r;
    asm("cvt.rna.tf32.f32 %0, %1;" : "=r"(r) : "f"(x));
    return r;   // f32 bit layout, low 13 mantissa bits zeroed
}
__device__ __forceinline__ void mma_tf32(float* d, const uint32_t* a, const uint32_t* b) {
    asm volatile(
        "mma.sync.aligned.m16n8k8.row.col.f32.tf32.tf32.f32 "
        "{%0,%1,%2,%3}, {%4,%5,%6,%7}, {%8,%9}, {%0,%1,%2,%3};"
        : "+f"(d[0]), "+f"(d[1]), "+f"(d[2]), "+f"(d[3])
        : "r"(a[0]), "r"(a[1]), "r"(a[2]), "r"(a[3]), "r"(b[0]), "r"(b[1]));
}
__device__ __forceinline__ void cpasync16(uint32_t saddr, const void* g) {
    asm volatile("cp.async.cg.shared.global [%0], [%1], 16;" :: "r"(saddr), "l"(g));
}

// ---------------- Embedding gather (tf32-rounded output) ----------------
__global__ __launch_bounds__(256) void embed_kernel(const int* __restrict__ ids,
                                                    const float* __restrict__ emb) {
    int idx = blockIdx.x * blockDim.x + threadIdx.x;
    int token = idx >> 8;                              // DM/4 = 256
    int d4 = idx & 255;
    int id = ids[token];
    float4 v = reinterpret_cast<const float4*>(emb + (size_t)id * DM)[d4];
    float4 o;
    o.x = __uint_as_float(f2tf32(v.x));
    o.y = __uint_as_float(f2tf32(v.y));
    o.z = __uint_as_float(f2tf32(v.z));
    o.w = __uint_as_float(f2tf32(v.w));
    reinterpret_cast<float4*>(g_x)[idx] = o;
}

// ---------------- Pre-round array to tf32 format ----------------
__global__ __launch_bounds__(256) void round_tf32_kernel(const float* __restrict__ in,
                                                         float* __restrict__ out) {
    size_t idx = (size_t)blockIdx.x * blockDim.x + threadIdx.x;   // over float4 elems
    float4 v = reinterpret_cast<const float4*>(in)[idx];
    float4 o;
    o.x = __uint_as_float(f2tf32(v.x));
    o.y = __uint_as_float(f2tf32(v.y));
    o.z = __uint_as_float(f2tf32(v.z));
    o.w = __uint_as_float(f2tf32(v.w));
    reinterpret_cast<float4*>(out)[idx] = o;
}

// ---------------- Pipelined TF32 GEMM: C[M,N] = A[M,K]*B[N,K]^T (+bias1+bias2) ----------
// 128 threads / 128x128 tile, 2 CTAs per SM (cross-CTA overlap hides the per-iter
// sync/wait/LDS head). 4 warps (2m x 2n), warp tile 64x64, BK=16, 3-stage cp.async.
// Fragment loads: one LDS.128 covering logical k = 4*lc..4*lc+3, split across the two
// MMAs (ks0 uses .x/.y, ks1 uses .z/.w); same k-slot map for A and B (exact math).
#define PBM 128
#define PBN 128
#define PBK 16
#define PSTR 16
#define PSTAGES 3
#define PASTG (PBM*PSTR)
#define PBSTG (PBN*PSTR)
#define PSMEM_BYTES (PSTAGES*(PASTG+PBSTG)*4)   // 49152 per CTA

__global__ __launch_bounds__(128, 2) void mma_tf32_pipe_kernel(
    const float* __restrict__ A, const float* __restrict__ B,
    const float* __restrict__ bias1, const float* __restrict__ bias2,
    float* __restrict__ C, int M, int N, int K)
{
    extern __shared__ float smem[];
    float* As = smem;                       // [PSTAGES][PASTG]
    float* Bs = smem + PSTAGES * PASTG;     // [PSTAGES][PBSTG]

    int tid = threadIdx.x, lane = tid & 31, wid = tid >> 5;
    int wm = wid & 1, wn = wid >> 1;        // 2x2 warp grid
    int m0 = wm * 64, n0 = wn * 64;
    int lr = lane >> 2, lc = lane & 3;

    int bm = blockIdx.x * PBM;
    int bn = blockIdx.y * PBN;

    // cp.async mapping: per stage A/B each 128 rows x 4 granules = 512 granules,
    // 128 threads -> 4 granules each (j = 0..3)
    const float* Ag[4];
    const float* Bg[4];
    uint32_t sAo[4], sBo[4];
    #pragma unroll
    for (int j = 0; j < 4; j++) {
        int idx = tid + j * 128;
        int row = idx >> 2, kc = idx & 3;
        Ag[j] = A + (size_t)(bm + row) * K + kc * 4;
        Bg[j] = B + (size_t)(bn + row) * K + kc * 4;
        sAo[j] = (uint32_t)__cvta_generic_to_shared(As + row * PSTR + kc * 4);
        sBo[j] = (uint32_t)__cvta_generic_to_shared(Bs + row * PSTR + kc * 4);
    }

    float acc[4][8][4];
    #pragma unroll
    for (int mf = 0; mf < 4; mf++)
        #pragma unroll
        for (int nf = 0; nf < 8; nf++)
            #pragma unroll
            for (int r = 0; r < 4; r++) acc[mf][nf][r] = 0.f;

    const int NIT = K / PBK;

    auto load_stage = [&](int s, int kt) {
        uint32_t aoff = s * PASTG * 4;
        uint32_t boff = s * PBSTG * 4;
        int g = kt * PBK;
        #pragma unroll
        for (int j = 0; j < 4; j++) {
            cpasync16(sAo[j] + aoff, Ag[j] + g);
            cpasync16(sBo[j] + boff, Bg[j] + g);
        }
    };

    load_stage(0, 0);
    asm volatile("cp.async.commit_group;");
    load_stage(1, 1);
    asm volatile("cp.async.commit_group;");

    int s = 0;
    for (int kt = 0; kt < NIT; kt++) {
        asm volatile("cp.async.wait_group 1;");
        __syncthreads();
        if (kt + 2 < NIT) load_stage((kt + 2) % PSTAGES, kt + 2);
        asm volatile("cp.async.commit_group;");

        const float* Asp = As + s * PASTG;
        const float* Bsp = Bs + s * PBSTG;

        // vector fragment loads: 16 x LDS.128 per warp-iteration
        float4 af4[4][2];   // [mf][0]=row, [1]=row+8 ; elems = logical k 4lc..4lc+3
        float4 bf4[8];      // [nf] col = n0+nf*8+lr
        #pragma unroll
        for (int mf = 0; mf < 4; mf++) {
            int row = m0 + mf * 16 + lr;
            af4[mf][0] = *reinterpret_cast<const float4*>(&Asp[row * PSTR + lc * 4]);
            af4[mf][1] = *reinterpret_cast<const float4*>(&Asp[(row + 8) * PSTR + lc * 4]);
        }
        #pragma unroll
        for (int nf = 0; nf < 8; nf++) {
            int col = n0 + nf * 8 + lr;
            bf4[nf] = *reinterpret_cast<const float4*>(&Bsp[col * PSTR + lc * 4]);
        }

        // ks0: logical k in {4j, 4j+1}, ks1: {4j+2, 4j+3}
        #pragma unroll
        for (int ks = 0; ks < 2; ks++) {
            uint32_t af[4][4], bf[8][2];
            #pragma unroll
            for (int mf = 0; mf < 4; mf++) {
                const float4& r0 = af4[mf][0];
                const float4& r1 = af4[mf][1];
                af[mf][0] = __float_as_uint(ks ? r0.z : r0.x);
                af[mf][1] = __float_as_uint(ks ? r1.z : r1.x);
                af[mf][2] = __float_as_uint(ks ? r0.w : r0.y);
                af[mf][3] = __float_as_uint(ks ? r1.w : r1.y);
            }
            #pragma unroll
            for (int nf = 0; nf < 8; nf++) {
                const float4& c0 = bf4[nf];
                bf[nf][0] = __float_as_uint(ks ? c0.z : c0.x);
                bf[nf][1] = __float_as_uint(ks ? c0.w : c0.y);
            }
            #pragma unroll
            for (int mf = 0; mf < 4; mf++)
                #pragma unroll
                for (int nf = 0; nf < 8; nf++)
                    mma_tf32(acc[mf][nf], af[mf], bf[nf]);
        }
        s++; if (s == PSTAGES) s = 0;
    }

    #pragma unroll
    for (int mf = 0; mf < 4; mf++) {
        int row = bm + m0 + mf * 16 + lr;
        #pragma unroll
        for (int nf = 0; nf < 8; nf++) {
            int col = bn + n0 + nf * 8 + lc * 2;
            float bs0 = 0.f, bs1 = 0.f;
            if (bias1) { bs0 += bias1[col]; bs1 += bias1[col + 1]; }
            if (bias2) { bs0 += bias2[col]; bs1 += bias2[col + 1]; }
            float2 v0 = make_float2(acc[mf][nf][0] + bs0, acc[mf][nf][1] + bs1);
            float2 v1 = make_float2(acc[mf][nf][2] + bs0, acc[mf][nf][3] + bs1);
            *reinterpret_cast<float2*>(&C[(size_t)row * N + col]) = v0;
            *reinterpret_cast<float2*>(&C[(size_t)(row + 8) * N + col]) = v1;
        }
    }
}

// ---------------- Grid barrier (persistent kernel, 128 co-resident blocks) ----------------
__device__ __forceinline__ void grid_barrier() {
    __threadfence();
    __syncthreads();
    if (threadIdx.x == 0) {
        unsigned int ticket = atomicAdd(&g_barrier_count, 1);
        unsigned int target = ticket - (ticket % gridDim.x) + gridDim.x;
        volatile unsigned int* p = &g_barrier_count;
        while ((int)(*p - target) < 0) { }
    }
    __syncthreads();
}

__device__ __forceinline__ float sigmoidf_(float x) { return 1.f / (1.f + expf(-x)); }

// ---------------- LSTM layer (persistent; tensor-core recurrence) ----------------
#define LSTM_BLOCKS 128
#define LSTM_THREADS 512

__global__ __launch_bounds__(LSTM_THREADS, 1) void lstm_layer_kernel(
    const float* __restrict__ Gx, const float* __restrict__ Wh,
    float* __restrict__ H, float* __restrict__ hn, float* __restrict__ cn,
    int round_out)
{
    __shared__ __align__(16) float sh[DM * BB];   // h_prev [k][b], 32KB (tf32 values)
    __shared__ float  sred[16 * 288];             // partials: [w][n*9 + b], stride-9 pad
    __shared__ float  sgate[256];                 // gates: [n][b]

    int tid  = threadIdx.x;
    int w    = tid >> 5;                   // warp id = k-slice 0..15 (k in [w*64,+64))
    int lane = tid & 31;
    int lr = lane >> 2, lc = lane & 3;     // fragment row/col

    // One-time: build Wh B-fragments (tf32) in registers.
    uint32_t wfrag[8][4][2];
    #pragma unroll
    for (int kt = 0; kt < 8; kt++)
        #pragma unroll
        for (int nf = 0; nf < 4; nf++) {
            int n = nf * 8 + lr;
            int grow = (n >> 3) * DM + blockIdx.x * 8 + (n & 7);
            const float* wr = Wh + (size_t)grow * DM + w * 64 + kt * 8;
            wfrag[kt][nf][0] = f2tf32(wr[lc]);
            wfrag[kt][nf][1] = f2tf32(wr[4 + lc]);
        }

    int rr = tid >> 3, bb = tid & 7;
    int grow_red = (rr >> 3) * DM + blockIdx.x * 8 + (rr & 7);

    float c_state = 0.f;
    int a_dl = tid >> 3, a_b = tid & 7;
    int a_d  = blockIdx.x * 8 + a_dl;

    for (int t = 0; t < SS; t++) {
        if (t > 0) {
            const float4* hb4 = reinterpret_cast<const float4*>(g_hbuf + ((t-1)&1) * (BB*DM));
            #pragma unroll
            for (int i = tid; i < BB * 256; i += LSTM_THREADS)
                reinterpret_cast<float4*>(sh)[i] = __ldcg(hb4 + i);
        }
        __syncthreads();

        float gx = 0.f;
        if (tid < 256)
            gx = __ldg(Gx + (size_t)(bb * SS + t) * G4D + grow_red);

        float acc[4][4];
        #pragma unroll
        for (int nf = 0; nf < 4; nf++)
            #pragma unroll
            for (int r = 0; r < 4; r++) acc[nf][r] = 0.f;
        if (t > 0) {
            const float* shw = sh + (size_t)(w * 64) * BB;
            #pragma unroll
            for (int kt = 0; kt < 8; kt++) {
                uint32_t af[4];
                af[0] = __float_as_uint(shw[(kt * 8 + lc) * BB + lr]);
                af[1] = 0u;
                af[2] = __float_as_uint(shw[(kt * 8 + 4 + lc) * BB + lr]);
                af[3] = 0u;
                #pragma unroll
                for (int nf = 0; nf < 4; nf++)
                    mma_tf32(acc[nf], af, wfrag[kt][nf]);
            }
        }

        #pragma unroll
        for (int nf = 0; nf < 4; nf++) {
            int n0 = nf * 8 + 2 * lc;
            sred[w * 288 + n0 * 9 + lr]       = acc[nf][0];
            sred[w * 288 + (n0 + 1) * 9 + lr] = acc[nf][1];
        }
        __syncthreads();

        if (tid < 256) {
            float sgx = gx;
            #pragma unroll
            for (int ww = 0; ww < 16; ww++)
                sgx += sred[ww * 288 + rr * 9 + bb];
            sgate[rr * 8 + bb] = sgx;
        }
        __syncthreads();

        if (tid < 64) {
            float gi = sgate[(0  + a_dl) * 8 + a_b];
            float gf = sgate[(8  + a_dl) * 8 + a_b];
            float go = sgate[(16 + a_dl) * 8 + a_b];
            float gg = sgate[(24 + a_dl) * 8 + a_b];
            float i_s = sigmoidf_(gi);
            float f_s = sigmoidf_(gf);
            float o_s = sigmoidf_(go);
            c_state = f_s * c_state + i_s * tanhf(gg);
            float h_new = o_s * tanhf(c_state);
            float h_store = round_out ? __uint_as_float(f2tf32(h_new)) : h_new;
            H[((size_t)(a_b * SS + t)) * DM + a_d] = h_store;
            g_hbuf[(t & 1) * (BB * DM) + a_d * BB + a_b] = __uint_as_float(f2tf32(h_new));
            if (t == SS - 1) {
                hn[a_b * DM + a_d] = h_new;    // exact
                cn[a_b * DM + a_d] = c_state;  // exact
            }
        }
        grid_barrier();
    }
}

// ---------------- RMSNorm (one block per row; emits tf32-rounded values) ----------------
__global__ __launch_bounds__(256) void rmsnorm_kernel(const float* __restrict__ in,
                                                      const float* __restrict__ w) {
    int row = blockIdx.x;
    int tid = threadIdx.x;
    const float4* r4 = reinterpret_cast<const float4*>(in + (size_t)row * DM);
    float4 v = r4[tid];
    float s = v.x*v.x + v.y*v.y + v.z*v.z + v.w*v.w;
    #pragma unroll
    for (int o = 16; o; o >>= 1) s += __shfl_xor_sync(0xFFFFFFFFu, s, o);
    __shared__ float red[8];
    if ((tid & 31) == 0) red[tid >> 5] = s;
    __syncthreads();
    float tot = red[0]+red[1]+red[2]+red[3]+red[4]+red[5]+red[6]+red[7];
    float scale = rsqrtf(tot * (1.f/ (float)DM) + 1e-5f);
    float4 wv = reinterpret_cast<const float4*>(w)[tid];
    float4 o4;
    o4.x = __uint_as_float(f2tf32(v.x * scale * wv.x));
    o4.y = __uint_as_float(f2tf32(v.y * scale * wv.y));
    o4.z = __uint_as_float(f2tf32(v.z * scale * wv.z));
    o4.w = __uint_as_float(f2tf32(v.w * scale * wv.w));
    reinterpret_cast<float4*>(g_norm + (size_t)row * DM)[tid] = o4;
}

// ---------------- Launch ----------------
extern "C" void kernel_launch(void* const* d_in, const int* in_sizes, int n_in,
                              void* d_out, int out_size) {
    const int*   ids = (const int*)d_in[0];
    const float* emb = (const float*)d_in[1];
    const float* Wx  = (const float*)d_in[2];
    const float* bx  = (const float*)d_in[3];
    const float* Wh  = (const float*)d_in[4];
    const float* bh  = (const float*)d_in[5];
    const float* nw  = (const float*)d_in[6];
    const float* ow  = (const float*)d_in[7];

    float* out = (float*)d_out;
    float* logits = out;
    float* hn = out + (size_t)M_ROWS * VOCAB;
    float* cn = hn + (size_t)NL * BB * DM;

    float *px, *pgx, *pH0, *pH1, *pnorm, *powt, *pwxt;
    cudaGetSymbolAddress((void**)&px,    g_x);
    cudaGetSymbolAddress((void**)&pgx,   g_gx);
    cudaGetSymbolAddress((void**)&pH0,   g_H0);
    cudaGetSymbolAddress((void**)&pH1,   g_H1);
    cudaGetSymbolAddress((void**)&pnorm, g_norm);
    cudaGetSymbolAddress((void**)&powt,  g_owt);
    cudaGetSymbolAddress((void**)&pwxt,  g_wxt);

    static bool attr_done = false;
    if (!attr_done) {
        cudaFuncSetAttribute(mma_tf32_pipe_kernel,
                             cudaFuncAttributeMaxDynamicSharedMemorySize, PSMEM_BYTES);
        attr_done = true;
    }

    // 0. pre-round weights to tf32 (independent of everything else)
    round_tf32_kernel<<<(VOCAB/4) * (DM/256), 256>>>(ow, powt);
    round_tf32_kernel<<<(NL * G4D * DM / 4) / 256, 256>>>(Wx, pwxt);

    // 1. embeddings (tf32-rounded; feeds gate GEMM only)
    embed_kernel<<<M_ROWS * (DM/4) / 256, 256>>>(ids, emb);

    // 2. layer 0 x-gates (tf32 tensor cores, +bx0+bh0)
    mma_tf32_pipe_kernel<<<dim3(M_ROWS/PBM, G4D/PBN), 128, PSMEM_BYTES>>>(
        px, pwxt, bx, bh, pgx, M_ROWS, G4D, DM);

    // 3. layer 0 recurrence (tensor-core; H0 written tf32-rounded)
    lstm_layer_kernel<<<LSTM_BLOCKS, LSTM_THREADS>>>(pgx, Wh, pH0, hn, cn, 1);

    // 4. layer 1 x-gates (tf32 tensor cores, +bx1+bh1)
    mma_tf32_pipe_kernel<<<dim3(M_ROWS/PBM, G4D/PBN), 128, PSMEM_BYTES>>>(
        pH0, pwxt + (size_t)G4D*DM, bx + G4D, bh + G4D, pgx, M_ROWS, G4D, DM);

    // 5. layer 1 recurrence (tensor-core; H1 exact fp32)
    lstm_layer_kernel<<<LSTM_BLOCKS, LSTM_THREADS>>>(pgx, Wh + (size_t)G4D*DM, pH1,
                                                     hn + BB*DM, cn + BB*DM, 0);

    // 6. RMSNorm (tf32-rounded output)
    rmsnorm_kernel<<<M_ROWS, 256>>>(pH1, nw);

    // 7. logits (pipelined tf32 mma.sync, 2 CTAs/SM)
    mma_tf32_pipe_kernel<<<dim3(M_ROWS/PBM, VOCAB/PBN), 128, PSMEM_BYTES>>>(
        pnorm, powt, nullptr, nullptr, logits, M_ROWS, VOCAB, DM);
}